// round 5
// baseline (speedup 1.0000x reference)
#include <cuda_runtime.h>
#include <cuda_bf16.h>
#include <cstdint>
#include <cstddef>

#define N_SRC   100000
#define N_DST   50000
#define NODE_IN 128
#define HID     64
#define GRID    152
#define NTILE   (N_DST / 8)

__device__ float g_P[(size_t)N_SRC * HID];
__device__ float g_R[(size_t)N_DST * HID];

// ---------------------------------------------------------------------------
__device__ __forceinline__ uint32_t smem_u32(const void* p) {
    uint32_t a;
    asm("{ .reg .u64 t; cvta.to.shared.u64 t, %1; cvt.u32.u64 %0, t; }" : "=r"(a) : "l"(p));
    return a;
}
__device__ __forceinline__ void ldsm4(uint32_t r[4], uint32_t addr) {
    asm volatile("ldmatrix.sync.aligned.m8n8.x4.shared.b16 {%0,%1,%2,%3}, [%4];"
        : "=r"(r[0]), "=r"(r[1]), "=r"(r[2]), "=r"(r[3]) : "r"(addr));
}
__device__ __forceinline__ void mma_bf16(float d[4], const uint32_t a[4],
                                         uint32_t b0, uint32_t b1) {
    asm volatile("mma.sync.aligned.m16n8k16.row.col.f32.bf16.bf16.f32 "
        "{%0,%1,%2,%3}, {%4,%5,%6,%7}, {%8,%9}, {%0,%1,%2,%3};"
        : "+f"(d[0]), "+f"(d[1]), "+f"(d[2]), "+f"(d[3])
        : "r"(a[0]), "r"(a[1]), "r"(a[2]), "r"(a[3]), "r"(b0), "r"(b1));
}
__device__ __forceinline__ void split2(float a, float b,
                                       __nv_bfloat162& h, __nv_bfloat162& l) {
    h = __floats2bfloat162_rn(a, b);
    const float2 f = __bfloat1622float2(h);
    l = __floats2bfloat162_rn(a - f.x, b - f.y);
}
__device__ __forceinline__ uint32_t b2u(__nv_bfloat162 v) { return *(uint32_t*)&v; }

// 3-pass bf16-split GEMM for k_projT (warp tile 32x32)
template<int KSTEPS, int STRIDE>
__device__ __forceinline__ void gemm_x3(uint32_t aH, uint32_t aL,
                                        uint32_t bH, uint32_t bL,
                                        int mrow, int ncol, int lane,
                                        float acc[2][4][4]) {
    const int arow = mrow + (lane & 15);
    const int asel = (lane >> 4) * 8;
    const int brow = ncol + ((lane >> 4) << 3) + (lane & 7);
    const int bsel = ((lane >> 3) & 1) * 8;
    #pragma unroll
    for (int ks = 0; ks < KSTEPS; ks++) {
        uint32_t ah[2][4], al[2][4], bh[2][4], bl[2][4];
        #pragma unroll
        for (int mt = 0; mt < 2; mt++) {
            const uint32_t off = (uint32_t)(((arow + mt * 16) * STRIDE + ks * 16 + asel) * 2);
            ldsm4(ah[mt], aH + off);
            ldsm4(al[mt], aL + off);
        }
        #pragma unroll
        for (int j = 0; j < 2; j++) {
            const uint32_t off = (uint32_t)(((brow + j * 16) * STRIDE + ks * 16 + bsel) * 2);
            ldsm4(bh[j], bH + off);
            ldsm4(bl[j], bL + off);
        }
        #pragma unroll
        for (int mt = 0; mt < 2; mt++)
            #pragma unroll
            for (int nt = 0; nt < 4; nt++) {
                const int j = nt >> 1, hf = (nt & 1) * 2;
                mma_bf16(acc[mt][nt], ah[mt], bh[j][hf], bh[j][hf + 1]);
                mma_bf16(acc[mt][nt], ah[mt], bl[j][hf], bl[j][hf + 1]);
                mma_bf16(acc[mt][nt], al[mt], bh[j][hf], bh[j][hf + 1]);
            }
    }
}

// ---------------------------------------------------------------------------
// Kernel 1: P = nf @ Wo_top, R = nf[:N_DST] @ Wn_top  (unchanged from R4)
// ---------------------------------------------------------------------------
#define POFF_AH 0
#define POFF_AL 34816
#define POFF_WH 69632
#define POFF_WL 87040
#define PJ_SMEM 104448
#define PJ_BLOCKS 296
#define PJ_PSPLIT 197

__global__ __launch_bounds__(256, 2)
void k_projT(const float* __restrict__ nf,
             const float* __restrict__ Wo,
             const float* __restrict__ Wn)
{
    extern __shared__ char smc[];
    const int tid = threadIdx.x, lane = tid & 31, wid = tid >> 5;
    const int mrow = (wid & 3) * 32, ncol = (wid >> 2) * 32;

    const bool isP = (blockIdx.x < PJ_PSPLIT);
    const float* W = isP ? Wo : Wn;
    float* dst = isP ? g_P : g_R;
    const int limit = isP ? N_SRC : N_DST;
    const int ntile = (limit + 127) >> 7;
    const int t0 = isP ? blockIdx.x : (blockIdx.x - PJ_PSPLIT);
    const int ts = isP ? PJ_PSPLIT : (PJ_BLOCKS - PJ_PSPLIT);

    for (int i = tid; i < 64 * 128; i += 256) {
        const int n = i >> 7, k = i & 127;
        const float w = W[k * 64 + n];
        const __nv_bfloat16 h = __float2bfloat16(w);
        ((__nv_bfloat16*)(smc + POFF_WH))[n * 136 + k] = h;
        ((__nv_bfloat16*)(smc + POFF_WL))[n * 136 + k] =
            __float2bfloat16(w - __bfloat162float(h));
    }
    const uint32_t aH = smem_u32(smc + POFF_AH), aL = smem_u32(smc + POFF_AL);
    const uint32_t bH = smem_u32(smc + POFF_WH), bL = smem_u32(smc + POFF_WL);

    for (int tile = t0; tile < ntile; tile += ts) {
        __syncthreads();
        const int base = tile * 128;
        #pragma unroll
        for (int t = 0; t < 16; t++) {
            const int idx = tid + 256 * t;
            const int r = idx >> 5, q = idx & 31;
            float4 v = make_float4(0.f, 0.f, 0.f, 0.f);
            if (base + r < limit)
                v = ((const float4*)(nf + (size_t)(base + r) * NODE_IN))[q];
            __nv_bfloat162 h0, l0, h1, l1;
            split2(v.x, v.y, h0, l0);
            split2(v.z, v.w, h1, l1);
            const size_t bo_ = (size_t)(r * 136 + 4 * q) * 2;
            *(uint2*)(smc + POFF_AH + bo_) = make_uint2(b2u(h0), b2u(h1));
            *(uint2*)(smc + POFF_AL + bo_) = make_uint2(b2u(l0), b2u(l1));
        }
        __syncthreads();

        float acc[2][4][4];
        #pragma unroll
        for (int a = 0; a < 2; a++)
            #pragma unroll
            for (int b = 0; b < 4; b++)
                #pragma unroll
                for (int c = 0; c < 4; c++) acc[a][b][c] = 0.f;

        gemm_x3<8, 136>(aH, aL, bH, bL, mrow, ncol, lane, acc);

        #pragma unroll
        for (int mt = 0; mt < 2; mt++) {
            const int r0 = base + mrow + mt * 16 + (lane >> 2);
            #pragma unroll
            for (int nt = 0; nt < 4; nt++) {
                const int c = ncol + nt * 8 + (lane & 3) * 2;
                if (r0 < limit)
                    *(float2*)(dst + (size_t)r0 * HID + c) =
                        make_float2(acc[mt][nt][0], acc[mt][nt][1]);
                if (r0 + 8 < limit)
                    *(float2*)(dst + (size_t)(r0 + 8) * HID + c) =
                        make_float2(acc[mt][nt][2], acc[mt][nt][3]);
            }
        }
    }
}

// ---------------------------------------------------------------------------
// Kernel 2: fused pipeline — 4 compute warps (fragment chaining) +
//           4 producer warps (double-buffered staging + logits + sparsemax)
// ---------------------------------------------------------------------------
#define OFF_EH0  0
#define OFF_EL0  18432
#define OFF_EH1  36864
#define OFF_EL1  55296
#define OFF_W1H  73728
#define OFF_W1L  82944
#define OFF_W2H  92160
#define OFF_W2L  101376
#define OFF_W3H  110592
#define OFF_W3L  119808
#define OFF_HNH  129024
#define OFF_HNL  131328
#define OFF_LOG  133632   // 2 x 128 floats
#define OFF_TAU  134656   // 2 x 8
#define OFF_AMX  134720   // 2 x 8
#define OFF_SRC  134784   // 2 x 128 ints
#define OFF_V    135808
#define OFF_BE   136064
#define OFF_BO   136320
#define OFF_BN   136576
#define OFF_C    136832
#define FS_SMEM  136848

// producer: stage one tile into buffer `buf`, fused logits + sparsemax
__device__ __forceinline__ void stage_tile(char* smc, const float* __restrict__ ef,
                                           const int* __restrict__ src_idx,
                                           int tile, int buf, int ptid, float cval)
{
    const size_t eh = buf ? OFF_EH1 : OFF_EH0;
    float* sLog = (float*)(smc + OFF_LOG) + buf * 128;
    const float* sV = (float*)(smc + OFF_V);
    const float4* eg = (const float4*)(ef + (size_t)tile * 8192);
    #pragma unroll
    for (int t = 0; t < 16; t++) {
        const int idx = ptid + 128 * t;          // 0..2047
        const int r = idx >> 4, q = idx & 15;
        const float4 v = eg[idx];
        __nv_bfloat162 h0, l0, h1, l1;
        split2(v.x, v.y, h0, l0);
        split2(v.z, v.w, h1, l1);
        const size_t bo_ = (size_t)(r * 72 + 4 * q) * 2;
        *(uint2*)(smc + eh + bo_)         = make_uint2(b2u(h0), b2u(h1));
        *(uint2*)(smc + eh + 18432 + bo_) = make_uint2(b2u(l0), b2u(l1));
        float p = v.x * sV[4 * q] + v.y * sV[4 * q + 1]
                + v.z * sV[4 * q + 2] + v.w * sV[4 * q + 3];
        p += __shfl_xor_sync(0xffffffffu, p, 1);
        p += __shfl_xor_sync(0xffffffffu, p, 2);
        p += __shfl_xor_sync(0xffffffffu, p, 4);
        p += __shfl_xor_sync(0xffffffffu, p, 8);
        if ((ptid & 15) == 0) sLog[r] = p;
    }
    ((int*)(smc + OFF_SRC))[buf * 128 + ptid] = src_idx[tile * 128 + ptid];
    asm volatile("bar.sync 2, 128;" ::: "memory");
    if (ptid < 8) {
        float z[16], amax = -3.4e38f;
        #pragma unroll
        for (int d = 0; d < 16; d++) {
            float raw = sLog[ptid * 16 + d] + cval;
            raw = (raw > 0.f) ? raw : 0.01f * raw;
            sLog[ptid * 16 + d] = raw;
            z[d] = raw; amax = fmaxf(amax, z[d]);
        }
        #pragma unroll
        for (int d = 0; d < 16; d++) z[d] -= amax;
        #pragma unroll
        for (int kk2 = 2; kk2 <= 16; kk2 <<= 1)
            #pragma unroll
            for (int j = kk2 >> 1; j > 0; j >>= 1)
                #pragma unroll
                for (int i = 0; i < 16; i++) {
                    const int l = i ^ j;
                    if (l > i) {
                        const bool up = ((i & kk2) == 0);
                        const float a0 = z[i], b0 = z[l];
                        if (up ? (a0 > b0) : (a0 < b0)) { z[i] = b0; z[l] = a0; }
                    }
                }
        float cs = 0.f, cssel = 0.f, kk = 1.f;
        #pragma unroll
        for (int j = 1; j <= 16; j++) {
            const float zz = z[16 - j];
            cs += zz;
            if (1.f + (float)j * zz > cs) { kk = (float)j; cssel = cs; }
        }
        ((float*)(smc + OFF_TAU))[buf * 8 + ptid] = (cssel - 1.f) / kk;
        ((float*)(smc + OFF_AMX))[buf * 8 + ptid] = amax;
    }
}

__global__ __launch_bounds__(256, 1)
void k_fusedT(const float* __restrict__ ef,
              const int*   __restrict__ src_idx,
              const float* __restrict__ We,  const float* __restrict__ be,
              const float* __restrict__ Wa,  const float* __restrict__ ba,
              const float* __restrict__ wa,
              const float* __restrict__ Wo,  const float* __restrict__ bo,
              const float* __restrict__ Wn,  const float* __restrict__ bn,
              float* __restrict__ out)
{
    extern __shared__ char smc[];
    const int tid = threadIdx.x, lane = tid & 31, wid = tid >> 5;

    // ---- one-time staging (all threads) ----
    for (int i = tid; i < 4096; i += 256) {
        const int n = i >> 6, k = i & 63;
        const float w1 = We[k * 64 + n];
        const float w2 = Wo[(NODE_IN + k) * 64 + n];
        const float w3 = Wn[(NODE_IN + k) * 64 + n];
        const __nv_bfloat16 h1 = __float2bfloat16(w1);
        const __nv_bfloat16 h2 = __float2bfloat16(w2);
        const __nv_bfloat16 h3 = __float2bfloat16(w3);
        ((__nv_bfloat16*)(smc + OFF_W1H))[n * 72 + k] = h1;
        ((__nv_bfloat16*)(smc + OFF_W1L))[n * 72 + k] = __float2bfloat16(w1 - __bfloat162float(h1));
        ((__nv_bfloat16*)(smc + OFF_W2H))[n * 72 + k] = h2;
        ((__nv_bfloat16*)(smc + OFF_W2L))[n * 72 + k] = __float2bfloat16(w2 - __bfloat162float(h2));
        ((__nv_bfloat16*)(smc + OFF_W3H))[n * 72 + k] = h3;
        ((__nv_bfloat16*)(smc + OFF_W3L))[n * 72 + k] = __float2bfloat16(w3 - __bfloat162float(h3));
    }
    for (int i = tid; i < 576; i += 256) {   // zero full HN (16 x 72 x hi/lo)
        ((uint32_t*)(smc + OFF_HNH))[i] = 0;
        ((uint32_t*)(smc + OFF_HNL))[i] = 0;
    }
    if (tid < 64) {
        ((float*)(smc + OFF_BE))[tid] = be[tid];
        ((float*)(smc + OFF_BO))[tid] = bo[tid];
        ((float*)(smc + OFF_BN))[tid] = bn[tid];
        float sv = 0.f;
        #pragma unroll 8
        for (int k = 0; k < 64; k++) sv = fmaf(Wa[tid * 64 + k], wa[k], sv);
        ((float*)(smc + OFF_V))[tid] = sv;
    }
    if (tid == 64) {
        float sc = 0.f;
        for (int k = 0; k < 64; k++) sc = fmaf(ba[k], wa[k], sc);
        *(float*)(smc + OFF_C) = sc;
    }
    __syncthreads();
    const float cval = *(const float*)(smc + OFF_C);

    const uint32_t smb = smem_u32(smc);
    const uint32_t w1H = smb + OFF_W1H, w1L = smb + OFF_W1L;
    const uint32_t w2H = smb + OFF_W2H, w2L = smb + OFF_W2L;
    const uint32_t w3H = smb + OFF_W3H, w3L = smb + OFF_W3L;
    const uint32_t hnH = smb + OFF_HNH, hnL = smb + OFF_HNL;

    // prologue: producers stage tile0 into buf0
    if (wid >= 4 && blockIdx.x < NTILE)
        stage_tile(smc, ef, src_idx, blockIdx.x, 0, tid - 128, cval);
    __syncthreads();

    int bufc = 0;
    for (int tile = blockIdx.x; tile < NTILE; tile += GRID) {
        if (wid < 4) {
            // ================= CONSUMER =================
            const uint32_t eH = smb + (bufc ? OFF_EH1 : OFF_EH0);
            const uint32_t eL = eH + 18432;
            const int arow = (wid << 5) + (lane & 15);
            const int asel = (lane >> 4) * 8;
            const int bro  = ((lane >> 4) << 3) + (lane & 7);
            const int bsel = ((lane >> 3) & 1) * 8;

            // ---- GEMM1: D1 = E @ We^T  (warp tile 32 x 64) ----
            float d1[2][8][4];
            #pragma unroll
            for (int a = 0; a < 2; a++)
                #pragma unroll
                for (int b = 0; b < 8; b++)
                    #pragma unroll
                    for (int c = 0; c < 4; c++) d1[a][b][c] = 0.f;
            #pragma unroll
            for (int ks = 0; ks < 4; ks++) {
                uint32_t ah[2][4], al[2][4], bh[4][4], bl[4][4];
                #pragma unroll
                for (int mt = 0; mt < 2; mt++) {
                    const uint32_t off = (uint32_t)(((arow + 16 * mt) * 72 + ks * 16 + asel) * 2);
                    ldsm4(ah[mt], eH + off);
                    ldsm4(al[mt], eL + off);
                }
                #pragma unroll
                for (int g = 0; g < 4; g++) {
                    const uint32_t off = (uint32_t)(((16 * g + bro) * 72 + ks * 16 + bsel) * 2);
                    ldsm4(bh[g], w1H + off);
                    ldsm4(bl[g], w1L + off);
                }
                #pragma unroll
                for (int mt = 0; mt < 2; mt++)
                    #pragma unroll
                    for (int g = 0; g < 4; g++)
                        #pragma unroll
                        for (int sub = 0; sub < 2; sub++) {
                            float* d = d1[mt][2 * g + sub];
                            mma_bf16(d, ah[mt], bh[g][2 * sub], bh[g][2 * sub + 1]);
                            mma_bf16(d, ah[mt], bl[g][2 * sub], bl[g][2 * sub + 1]);
                            mma_bf16(d, al[mt], bh[g][2 * sub], bh[g][2 * sub + 1]);
                        }
            }

            // ---- epilogue1 IN REGISTERS: relu(+be) -> A2 fragments ----
            uint32_t a2h[2][4][4], a2l[2][4][4];
            const float* sBe = (const float*)(smc + OFF_BE);
            #pragma unroll
            for (int mt = 0; mt < 2; mt++)
                #pragma unroll
                for (int ks = 0; ks < 4; ks++)
                    #pragma unroll
                    for (int h2 = 0; h2 < 2; h2++) {
                        const int nt = 2 * ks + h2;
                        const float2 be2 = *(const float2*)(sBe + nt * 8 + (lane & 3) * 2);
                        const float x0 = fmaxf(d1[mt][nt][0] + be2.x, 0.f);
                        const float x1 = fmaxf(d1[mt][nt][1] + be2.y, 0.f);
                        const float x2 = fmaxf(d1[mt][nt][2] + be2.x, 0.f);
                        const float x3 = fmaxf(d1[mt][nt][3] + be2.y, 0.f);
                        __nv_bfloat162 hA, lA, hB, lB;
                        split2(x0, x1, hA, lA);
                        split2(x2, x3, hB, lB);
                        a2h[mt][ks][2 * h2]     = b2u(hA);
                        a2h[mt][ks][2 * h2 + 1] = b2u(hB);
                        a2l[mt][ks][2 * h2]     = b2u(lA);
                        a2l[mt][ks][2 * h2 + 1] = b2u(lB);
                    }

            // ---- GEMM2: acc = e_out @ Wo_bot^T  (A from registers!) ----
            float acc[2][8][4];
            #pragma unroll
            for (int a = 0; a < 2; a++)
                #pragma unroll
                for (int b = 0; b < 8; b++)
                    #pragma unroll
                    for (int c = 0; c < 4; c++) acc[a][b][c] = 0.f;
            #pragma unroll
            for (int ks = 0; ks < 4; ks++) {
                uint32_t bh[4][4], bl[4][4];
                #pragma unroll
                for (int g = 0; g < 4; g++) {
                    const uint32_t off = (uint32_t)(((16 * g + bro) * 72 + ks * 16 + bsel) * 2);
                    ldsm4(bh[g], w2H + off);
                    ldsm4(bl[g], w2L + off);
                }
                #pragma unroll
                for (int mt = 0; mt < 2; mt++)
                    #pragma unroll
                    for (int g = 0; g < 4; g++)
                        #pragma unroll
                        for (int sub = 0; sub < 2; sub++) {
                            float* d = acc[mt][2 * g + sub];
                            mma_bf16(d, a2h[mt][ks], bh[g][2 * sub], bh[g][2 * sub + 1]);
                            mma_bf16(d, a2h[mt][ks], bl[g][2 * sub], bl[g][2 * sub + 1]);
                            mma_bf16(d, a2l[mt][ks], bh[g][2 * sub], bh[g][2 * sub + 1]);
                        }
            }

            // ---- epilogue2: m = relu(acc + P[src] + bo), alpha-weight, reduce ----
            const float* sLog = (const float*)(smc + OFF_LOG) + bufc * 128;
            const float* sTau = (const float*)(smc + OFF_TAU) + bufc * 8;
            const float* sAmx = (const float*)(smc + OFF_AMX) + bufc * 8;
            const int*   sSrc = (const int*)(smc + OFF_SRC) + bufc * 128;
            const float* sBo  = (const float*)(smc + OFF_BO);
            #pragma unroll
            for (int mt = 0; mt < 2; mt++) {
                const int ln = 2 * wid + mt;
                const int r0 = 32 * wid + 16 * mt + (lane >> 2);
                const int r1 = r0 + 8;
                const int s0 = sSrc[r0], s1 = sSrc[r1];
                const float at = sAmx[ln] + sTau[ln];
                const float al0 = fmaxf(sLog[r0] - at, 0.f);
                const float al1 = fmaxf(sLog[r1] - at, 0.f);
                #pragma unroll
                for (int nt = 0; nt < 8; nt++) {
                    const int c = nt * 8 + (lane & 3) * 2;
                    const float2 bo2 = *(const float2*)(sBo + c);
                    const float2 p0 = *(const float2*)(g_P + (size_t)s0 * HID + c);
                    const float2 p1 = *(const float2*)(g_P + (size_t)s1 * HID + c);
                    const float m00 = fmaxf(acc[mt][nt][0] + p0.x + bo2.x, 0.f);
                    const float m01 = fmaxf(acc[mt][nt][1] + p0.y + bo2.y, 0.f);
                    const float m10 = fmaxf(acc[mt][nt][2] + p1.x + bo2.x, 0.f);
                    const float m11 = fmaxf(acc[mt][nt][3] + p1.y + bo2.y, 0.f);
                    float sx = m00 * al0 + m10 * al1;
                    float sy = m01 * al0 + m11 * al1;
                    sx += __shfl_xor_sync(0xffffffffu, sx, 4);
                    sy += __shfl_xor_sync(0xffffffffu, sy, 4);
                    sx += __shfl_xor_sync(0xffffffffu, sx, 8);
                    sy += __shfl_xor_sync(0xffffffffu, sy, 8);
                    sx += __shfl_xor_sync(0xffffffffu, sx, 16);
                    sy += __shfl_xor_sync(0xffffffffu, sy, 16);
                    if (lane < 4) {
                        __nv_bfloat162 hh, ll;
                        split2(sx, sy, hh, ll);
                        *(uint32_t*)(smc + OFF_HNH + (size_t)(ln * 72 + c) * 2) = b2u(hh);
                        *(uint32_t*)(smc + OFF_HNL + (size_t)(ln * 72 + c) * 2) = b2u(ll);
                    }
                }
            }
            asm volatile("bar.sync 1, 128;" ::: "memory");

            // ---- GEMM3: out = relu(R + HN @ Wn_bot^T + bn), warp owns 16 cols ----
            {
                float acc3[2][4] = {{0.f, 0.f, 0.f, 0.f}, {0.f, 0.f, 0.f, 0.f}};
                #pragma unroll
                for (int ks = 0; ks < 4; ks++) {
                    uint32_t a3h[4], a3l[4], b3h[4], b3l[4];
                    const uint32_t aoff = (uint32_t)(((lane & 15) * 72 + ks * 16 + (lane >> 4) * 8) * 2);
                    ldsm4(a3h, hnH + aoff);
                    ldsm4(a3l, hnL + aoff);
                    const uint32_t boff = (uint32_t)(((wid * 16 + bro) * 72 + ks * 16 + bsel) * 2);
                    ldsm4(b3h, w3H + boff);
                    ldsm4(b3l, w3L + boff);
                    #pragma unroll
                    for (int sub = 0; sub < 2; sub++) {
                        mma_bf16(acc3[sub], a3h, b3h[2 * sub], b3h[2 * sub + 1]);
                        mma_bf16(acc3[sub], a3h, b3l[2 * sub], b3l[2 * sub + 1]);
                        mma_bf16(acc3[sub], a3l, b3h[2 * sub], b3h[2 * sub + 1]);
                    }
                }
                const int node = tile * 8 + (lane >> 2);
                const float* sBn = (const float*)(smc + OFF_BN);
                #pragma unroll
                for (int sub = 0; sub < 2; sub++) {
                    const int col = wid * 16 + sub * 8 + (lane & 3) * 2;
                    const float2 r2 = *(const float2*)(g_R + (size_t)node * HID + col);
                    const float2 bn2 = *(const float2*)(sBn + col);
                    const float o0 = acc3[sub][0] + r2.x + bn2.x;
                    const float o1 = acc3[sub][1] + r2.y + bn2.y;
                    *(float2*)(out + (size_t)node * HID + col) =
                        make_float2(fmaxf(o0, 0.f), fmaxf(o1, 0.f));
                }
            }
        } else {
            // ================= PRODUCER =================
            const int t2 = tile + GRID;
            if (t2 < NTILE)
                stage_tile(smc, ef, src_idx, t2, bufc ^ 1, tid - 128, cval);
        }
        __syncthreads();
        bufc ^= 1;
    }
}

// ---------------------------------------------------------------------------
extern "C" void kernel_launch(void* const* d_in, const int* in_sizes, int n_in,
                              void* d_out, int out_size)
{
    const float* nf = (const float*)d_in[0];
    const float* ef = (const float*)d_in[1];
    const int*   si = (const int*)  d_in[2];
    const float* We = (const float*)d_in[3];
    const float* be = (const float*)d_in[4];
    const float* Wa = (const float*)d_in[5];
    const float* ba = (const float*)d_in[6];
    const float* wa = (const float*)d_in[7];
    const float* Wo = (const float*)d_in[8];
    const float* bo = (const float*)d_in[9];
    const float* Wn = (const float*)d_in[10];
    const float* bn = (const float*)d_in[11];
    float* out = (float*)d_out;

    cudaFuncSetAttribute(k_projT,  cudaFuncAttributeMaxDynamicSharedMemorySize, PJ_SMEM);
    cudaFuncSetAttribute(k_fusedT, cudaFuncAttributeMaxDynamicSharedMemorySize, FS_SMEM);

    k_projT<<<PJ_BLOCKS, 256, PJ_SMEM>>>(nf, Wo, Wn);
    k_fusedT<<<GRID, 256, FS_SMEM>>>(ef, si, We, be, Wa, ba, wa, Wo, bo, Wn, bn, out);
}

// round 6
// speedup vs baseline: 1.8780x; 1.8780x over previous
#include <cuda_runtime.h>
#include <cuda_fp16.h>
#include <cstdint>
#include <cstddef>

#define N_SRC   100000
#define N_DST   50000
#define NODE_IN 128
#define HID     64
#define NTILE   (N_DST / 8)

__device__ float g_P[(size_t)N_SRC * HID];
__device__ float g_R[(size_t)N_DST * HID];

// ---------------------------------------------------------------------------
__device__ __forceinline__ uint32_t smem_u32(const void* p) {
    uint32_t a;
    asm("{ .reg .u64 t; cvta.to.shared.u64 t, %1; cvt.u32.u64 %0, t; }" : "=r"(a) : "l"(p));
    return a;
}
__device__ __forceinline__ void ldsm4(uint32_t r[4], uint32_t addr) {
    asm volatile("ldmatrix.sync.aligned.m8n8.x4.shared.b16 {%0,%1,%2,%3}, [%4];"
        : "=r"(r[0]), "=r"(r[1]), "=r"(r[2]), "=r"(r[3]) : "r"(addr));
}
__device__ __forceinline__ void mma_f16(float d[4], const uint32_t a[4],
                                        uint32_t b0, uint32_t b1) {
    asm volatile("mma.sync.aligned.m16n8k16.row.col.f32.f16.f16.f32 "
        "{%0,%1,%2,%3}, {%4,%5,%6,%7}, {%8,%9}, {%0,%1,%2,%3};"
        : "+f"(d[0]), "+f"(d[1]), "+f"(d[2]), "+f"(d[3])
        : "r"(a[0]), "r"(a[1]), "r"(a[2]), "r"(a[3]), "r"(b0), "r"(b1));
}
__device__ __forceinline__ void split2h(float a, float b, __half2& h, __half2& l) {
    h = __floats2half2_rn(a, b);
    const float2 f = __half22float2(h);
    l = __floats2half2_rn(a - f.x, b - f.y);
}
__device__ __forceinline__ uint32_t h2u(__half2 v) { return *(uint32_t*)&v; }

// 2-pass fp16 GEMM: D(.x32 warp tile) += A(hi+lo) @ B(single)^T
template<int KSTEPS, int STRIDE>
__device__ __forceinline__ void gemm_2p(uint32_t aH, uint32_t aL, uint32_t bS,
                                        int mrow, int ncol, int lane,
                                        float acc[2][4][4]) {
    const int arow = mrow + (lane & 15);
    const int asel = (lane >> 4) * 8;
    const int brow = ncol + ((lane >> 4) << 3) + (lane & 7);
    const int bsel = ((lane >> 3) & 1) * 8;
    #pragma unroll
    for (int ks = 0; ks < KSTEPS; ks++) {
        uint32_t ah[2][4], al[2][4], bs[2][4];
        #pragma unroll
        for (int mt = 0; mt < 2; mt++) {
            const uint32_t off = (uint32_t)(((arow + mt * 16) * STRIDE + ks * 16 + asel) * 2);
            ldsm4(ah[mt], aH + off);
            ldsm4(al[mt], aL + off);
        }
        #pragma unroll
        for (int j = 0; j < 2; j++) {
            const uint32_t off = (uint32_t)(((brow + j * 16) * STRIDE + ks * 16 + bsel) * 2);
            ldsm4(bs[j], bS + off);
        }
        #pragma unroll
        for (int mt = 0; mt < 2; mt++)
            #pragma unroll
            for (int nt = 0; nt < 4; nt++) {
                const int j = nt >> 1, hf = (nt & 1) * 2;
                mma_f16(acc[mt][nt], ah[mt], bs[j][hf], bs[j][hf + 1]);
                mma_f16(acc[mt][nt], al[mt], bs[j][hf], bs[j][hf + 1]);
            }
    }
}

// ---------------------------------------------------------------------------
// Kernel 1: P = nf @ Wo_top, R = nf[:N_DST] @ Wn_top
// ---------------------------------------------------------------------------
#define POFF_AH 0
#define POFF_AL 34816
#define POFF_W  69632
#define PJ_SMEM 87040
#define PJ_BLOCKS 296
#define PJ_PSPLIT 197

__global__ __launch_bounds__(256, 2)
void k_projT(const float* __restrict__ nf,
             const float* __restrict__ Wo,
             const float* __restrict__ Wn)
{
    extern __shared__ char smc[];
    const int tid = threadIdx.x, lane = tid & 31, wid = tid >> 5;
    const int mrow = (wid & 3) * 32, ncol = (wid >> 2) * 32;

    const bool isP = (blockIdx.x < PJ_PSPLIT);
    const float* W = isP ? Wo : Wn;
    float* dst = isP ? g_P : g_R;
    const int limit = isP ? N_SRC : N_DST;
    const int ntile = (limit + 127) >> 7;
    const int t0 = isP ? blockIdx.x : (blockIdx.x - PJ_PSPLIT);
    const int ts = isP ? PJ_PSPLIT : (PJ_BLOCKS - PJ_PSPLIT);

    // transposed weight single fp16: [n=64][k=128], stride 136
    for (int i = tid; i < 64 * 128; i += 256) {
        const int n = i >> 7, k = i & 127;
        ((__half*)(smc + POFF_W))[n * 136 + k] = __float2half(W[k * 64 + n]);
    }
    const uint32_t aH = smem_u32(smc + POFF_AH), aL = smem_u32(smc + POFF_AL);
    const uint32_t bS = smem_u32(smc + POFF_W);

    for (int tile = t0; tile < ntile; tile += ts) {
        __syncthreads();
        const int base = tile * 128;
        #pragma unroll
        for (int t = 0; t < 16; t++) {
            const int idx = tid + 256 * t;
            const int r = idx >> 5, q = idx & 31;
            float4 v = make_float4(0.f, 0.f, 0.f, 0.f);
            if (base + r < limit)
                v = ((const float4*)(nf + (size_t)(base + r) * NODE_IN))[q];
            __half2 h0, l0, h1, l1;
            split2h(v.x, v.y, h0, l0);
            split2h(v.z, v.w, h1, l1);
            const size_t bo_ = (size_t)(r * 136 + 4 * q) * 2;
            *(uint2*)(smc + POFF_AH + bo_) = make_uint2(h2u(h0), h2u(h1));
            *(uint2*)(smc + POFF_AL + bo_) = make_uint2(h2u(l0), h2u(l1));
        }
        __syncthreads();

        float acc[2][4][4];
        #pragma unroll
        for (int a = 0; a < 2; a++)
            #pragma unroll
            for (int b = 0; b < 4; b++)
                #pragma unroll
                for (int c = 0; c < 4; c++) acc[a][b][c] = 0.f;

        gemm_2p<8, 136>(aH, aL, bS, mrow, ncol, lane, acc);

        #pragma unroll
        for (int mt = 0; mt < 2; mt++) {
            const int r0 = base + mrow + mt * 16 + (lane >> 2);
            #pragma unroll
            for (int nt = 0; nt < 4; nt++) {
                const int c = ncol + nt * 8 + (lane & 3) * 2;
                if (r0 < limit)
                    *(float2*)(dst + (size_t)r0 * HID + c) =
                        make_float2(acc[mt][nt][0], acc[mt][nt][1]);
                if (r0 + 8 < limit)
                    *(float2*)(dst + (size_t)(r0 + 8) * HID + c) =
                        make_float2(acc[mt][nt][2], acc[mt][nt][3]);
            }
        }
    }
}

// ---------------------------------------------------------------------------
// Kernel 2: fused per-destination pipeline (R4 structure, fp16 2-pass)
// ---------------------------------------------------------------------------
#define OFF_EH   0
#define OFF_EL   18432
#define OFF_W1   36864
#define OFF_W2   46080
#define OFF_W3   55296
#define OFF_HNH  64512   // 16 x 72 fp16 (rows 8..15 stay zero)
#define OFF_HNL  66816
#define OFF_LOG  69120   // 128 floats
#define OFF_TAU  69632
#define OFF_AMX  69664
#define OFF_V    69696
#define OFF_BE   69952
#define OFF_BO   70208
#define OFF_BN   70464
#define OFF_SRC  70720
#define OFF_C    71232
#define FS_SMEM  71248

__global__ __launch_bounds__(256, 2)
void k_fusedT(const float* __restrict__ ef,
              const int*   __restrict__ src_idx,
              const float* __restrict__ We,  const float* __restrict__ be,
              const float* __restrict__ Wa,  const float* __restrict__ ba,
              const float* __restrict__ wa,
              const float* __restrict__ Wo,  const float* __restrict__ bo,
              const float* __restrict__ Wn,  const float* __restrict__ bn,
              float* __restrict__ out)
{
    extern __shared__ char smc[];
    const int tid = threadIdx.x, lane = tid & 31, wid = tid >> 5;
    const int mrow = (wid & 3) * 32, ncol = (wid >> 2) * 32;

    float* sLog = (float*)(smc + OFF_LOG);
    float* sTau = (float*)(smc + OFF_TAU);
    float* sAmx = (float*)(smc + OFF_AMX);
    float* sV   = (float*)(smc + OFF_V);
    float* sBe  = (float*)(smc + OFF_BE);
    float* sBo  = (float*)(smc + OFF_BO);
    float* sBn  = (float*)(smc + OFF_BN);
    int*   sSrc = (int*)  (smc + OFF_SRC);

    // one-time staging: 3 weight matrices single fp16 (stride 72), biases, v, c
    for (int i = tid; i < 4096; i += 256) {
        const int n = i >> 6, k = i & 63;
        ((__half*)(smc + OFF_W1))[n * 72 + k] = __float2half(We[k * 64 + n]);
        ((__half*)(smc + OFF_W2))[n * 72 + k] = __float2half(Wo[(NODE_IN + k) * 64 + n]);
        ((__half*)(smc + OFF_W3))[n * 72 + k] = __float2half(Wn[(NODE_IN + k) * 64 + n]);
    }
    // zero HN pad rows 8..15 (never written again)
    for (int i = tid; i < 288; i += 256) {
        ((uint32_t*)(smc + OFF_HNH + 1152))[i] = 0;
        ((uint32_t*)(smc + OFF_HNL + 1152))[i] = 0;
    }
    if (tid < 64) {
        sBe[tid] = be[tid]; sBo[tid] = bo[tid]; sBn[tid] = bn[tid];
        float sv = 0.f;
        #pragma unroll 8
        for (int k = 0; k < 64; k++) sv = fmaf(Wa[tid * 64 + k], wa[k], sv);
        sV[tid] = sv;
    }
    if (tid == 64) {
        float sc = 0.f;
        for (int k = 0; k < 64; k++) sc = fmaf(ba[k], wa[k], sc);
        *(float*)(smc + OFF_C) = sc;
    }
    __syncthreads();
    const float cval = *(const float*)(smc + OFF_C);

    const uint32_t eH = smem_u32(smc + OFF_EH), eL = smem_u32(smc + OFF_EL);
    const uint32_t w1 = smem_u32(smc + OFF_W1), w2 = smem_u32(smc + OFF_W2);
    const uint32_t w3 = smem_u32(smc + OFF_W3);
    const uint32_t hnH = smem_u32(smc + OFF_HNH), hnL = smem_u32(smc + OFF_HNL);

    // hoist GEMM3 B fragments (loop-invariant): warp owns cols wid*8..wid*8+7
    uint32_t b3[2][4];
    {
        const int nc = wid * 8;
        #pragma unroll
        for (int g = 0; g < 2; g++) {
            const uint32_t off = (uint32_t)(((nc + (lane & 7)) * 72 + (lane >> 3) * 8 + g * 32) * 2);
            ldsm4(b3[g], w3 + off);
        }
    }

    for (int tile = blockIdx.x; tile < NTILE; tile += gridDim.x) {
        __syncthreads();   // reuse guard (E, HN, sLog)

        // ---- stage E tile [128 x 64] -> hi/lo fp16 + fused fp32 logits ----
        const float4* eg = (const float4*)(ef + (size_t)tile * 8192);
        #pragma unroll
        for (int t = 0; t < 8; t++) {
            const int idx = tid + 256 * t;       // 0..2047
            const int r = idx >> 4, q = idx & 15;
            const float4 v = eg[idx];
            __half2 h0, l0, h1, l1;
            split2h(v.x, v.y, h0, l0);
            split2h(v.z, v.w, h1, l1);
            const size_t bo_ = (size_t)(r * 72 + 4 * q) * 2;
            *(uint2*)(smc + OFF_EH + bo_) = make_uint2(h2u(h0), h2u(h1));
            *(uint2*)(smc + OFF_EL + bo_) = make_uint2(h2u(l0), h2u(l1));
            float p = v.x * sV[4 * q] + v.y * sV[4 * q + 1]
                    + v.z * sV[4 * q + 2] + v.w * sV[4 * q + 3];
            p += __shfl_xor_sync(0xffffffffu, p, 1);
            p += __shfl_xor_sync(0xffffffffu, p, 2);
            p += __shfl_xor_sync(0xffffffffu, p, 4);
            p += __shfl_xor_sync(0xffffffffu, p, 8);
            if ((tid & 15) == 0) sLog[r] = p;
        }
        if (tid < 128) sSrc[tid] = src_idx[tile * 128 + tid];
        __syncthreads();

        // ---- sparsemax (8 threads) — overlaps with GEMM1 on other warps ----
        if (tid < 8) {
            float z[16], amax = -3.4e38f;
            #pragma unroll
            for (int d = 0; d < 16; d++) {
                float raw = sLog[tid * 16 + d] + cval;
                raw = (raw > 0.f) ? raw : 0.01f * raw;
                sLog[tid * 16 + d] = raw;
                z[d] = raw; amax = fmaxf(amax, z[d]);
            }
            #pragma unroll
            for (int d = 0; d < 16; d++) z[d] -= amax;
            #pragma unroll
            for (int kk2 = 2; kk2 <= 16; kk2 <<= 1)
                #pragma unroll
                for (int j = kk2 >> 1; j > 0; j >>= 1)
                    #pragma unroll
                    for (int i = 0; i < 16; i++) {
                        const int l = i ^ j;
                        if (l > i) {
                            const bool up = ((i & kk2) == 0);
                            const float a0 = z[i], b0 = z[l];
                            if (up ? (a0 > b0) : (a0 < b0)) { z[i] = b0; z[l] = a0; }
                        }
                    }
            float cs = 0.f, cssel = 0.f, kk = 1.f;
            #pragma unroll
            for (int j = 1; j <= 16; j++) {
                const float zz = z[16 - j];
                cs += zz;
                if (1.f + (float)j * zz > cs) { kk = (float)j; cssel = cs; }
            }
            sTau[tid] = (cssel - 1.f) / kk;
            sAmx[tid] = amax;
        }

        float acc[2][4][4];

        // ---- GEMM1: e_out_pre = E @ We^T ----
        #pragma unroll
        for (int a = 0; a < 2; a++)
            #pragma unroll
            for (int b = 0; b < 4; b++)
                #pragma unroll
                for (int c = 0; c < 4; c++) acc[a][b][c] = 0.f;
        gemm_2p<4, 72>(eH, eL, w1, mrow, ncol, lane, acc);
        __syncthreads();   // all E reads complete (e_out aliases E)

        // ---- epilogue1: relu(+be) -> fp16 hi/lo back into E buffers ----
        #pragma unroll
        for (int mt = 0; mt < 2; mt++) {
            const int r0 = mrow + mt * 16 + (lane >> 2);
            #pragma unroll
            for (int nt = 0; nt < 4; nt++) {
                const int c = ncol + nt * 8 + (lane & 3) * 2;
                const float x0 = fmaxf(acc[mt][nt][0] + sBe[c],     0.f);
                const float x1 = fmaxf(acc[mt][nt][1] + sBe[c + 1], 0.f);
                const float x2 = fmaxf(acc[mt][nt][2] + sBe[c],     0.f);
                const float x3 = fmaxf(acc[mt][nt][3] + sBe[c + 1], 0.f);
                __half2 h0, l0, h1, l1;
                split2h(x0, x1, h0, l0);
                split2h(x2, x3, h1, l1);
                *(uint32_t*)(smc + OFF_EH + (size_t)(r0 * 72 + c) * 2) = h2u(h0);
                *(uint32_t*)(smc + OFF_EL + (size_t)(r0 * 72 + c) * 2) = h2u(l0);
                *(uint32_t*)(smc + OFF_EH + (size_t)((r0 + 8) * 72 + c) * 2) = h2u(h1);
                *(uint32_t*)(smc + OFF_EL + (size_t)((r0 + 8) * 72 + c) * 2) = h2u(l1);
            }
        }
        __syncthreads();

        // ---- GEMM2: m_pre = e_out @ Wo_bot^T ----
        #pragma unroll
        for (int a = 0; a < 2; a++)
            #pragma unroll
            for (int b = 0; b < 4; b++)
                #pragma unroll
                for (int c = 0; c < 4; c++) acc[a][b][c] = 0.f;
        gemm_2p<4, 72>(eH, eL, w2, mrow, ncol, lane, acc);

        // ---- epilogue2: m = relu(m_pre + P[src] + bo); alpha-weighted sum ----
        #pragma unroll
        for (int mt = 0; mt < 2; mt++) {
            const int ln = (mrow >> 4) + mt;
            const int r0 = mrow + mt * 16 + (lane >> 2);
            const int r1 = r0 + 8;
            const int s0 = sSrc[r0], s1 = sSrc[r1];
            const float at = sAmx[ln] + sTau[ln];
            const float al0 = fmaxf(sLog[r0] - at, 0.f);
            const float al1 = fmaxf(sLog[r1] - at, 0.f);
            #pragma unroll
            for (int nt = 0; nt < 4; nt++) {
                const int c = ncol + nt * 8 + (lane & 3) * 2;
                const float2 p0 = *(const float2*)(g_P + (size_t)s0 * HID + c);
                const float2 p1 = *(const float2*)(g_P + (size_t)s1 * HID + c);
                const float m00 = fmaxf(acc[mt][nt][0] + p0.x + sBo[c],     0.f);
                const float m01 = fmaxf(acc[mt][nt][1] + p0.y + sBo[c + 1], 0.f);
                const float m10 = fmaxf(acc[mt][nt][2] + p1.x + sBo[c],     0.f);
                const float m11 = fmaxf(acc[mt][nt][3] + p1.y + sBo[c + 1], 0.f);
                float sx = m00 * al0 + m10 * al1;
                float sy = m01 * al0 + m11 * al1;
                sx += __shfl_xor_sync(0xffffffffu, sx, 4);
                sy += __shfl_xor_sync(0xffffffffu, sy, 4);
                sx += __shfl_xor_sync(0xffffffffu, sx, 8);
                sy += __shfl_xor_sync(0xffffffffu, sy, 8);
                sx += __shfl_xor_sync(0xffffffffu, sx, 16);
                sy += __shfl_xor_sync(0xffffffffu, sy, 16);
                if (lane < 4) {
                    __half2 hh, ll;
                    split2h(sx, sy, hh, ll);
                    *(uint32_t*)(smc + OFF_HNH + (size_t)(ln * 72 + c) * 2) = h2u(hh);
                    *(uint32_t*)(smc + OFF_HNL + (size_t)(ln * 72 + c) * 2) = h2u(ll);
                }
            }
        }
        __syncthreads();

        // ---- GEMM3 (MMA, M=16 padded): out = relu(R + HN @ Wn_bot^T + bn) ----
        {
            float acc3[4] = {0.f, 0.f, 0.f, 0.f};
            #pragma unroll
            for (int ks = 0; ks < 4; ks++) {
                uint32_t a3h[4], a3l[4];
                const uint32_t aoff = (uint32_t)(((lane & 15) * 72 + ks * 16 + (lane >> 4) * 8) * 2);
                ldsm4(a3h, hnH + aoff);
                ldsm4(a3l, hnL + aoff);
                const int g = ks >> 1, pr = (ks & 1) * 2;
                mma_f16(acc3, a3h, b3[g][pr], b3[g][pr + 1]);
                mma_f16(acc3, a3l, b3[g][pr], b3[g][pr + 1]);
            }
            const int node = tile * 8 + (lane >> 2);
            const int col = wid * 8 + (lane & 3) * 2;
            const float2 r2 = *(const float2*)(g_R + (size_t)node * HID + col);
            const float o0 = acc3[0] + r2.x + sBn[col];
            const float o1 = acc3[1] + r2.y + sBn[col + 1];
            *(float2*)(out + (size_t)node * HID + col) =
                make_float2(fmaxf(o0, 0.f), fmaxf(o1, 0.f));
        }
    }
}

// ---------------------------------------------------------------------------
extern "C" void kernel_launch(void* const* d_in, const int* in_sizes, int n_in,
                              void* d_out, int out_size)
{
    const float* nf = (const float*)d_in[0];
    const float* ef = (const float*)d_in[1];
    const int*   si = (const int*)  d_in[2];
    const float* We = (const float*)d_in[3];
    const float* be = (const float*)d_in[4];
    const float* Wa = (const float*)d_in[5];
    const float* ba = (const float*)d_in[6];
    const float* wa = (const float*)d_in[7];
    const float* Wo = (const float*)d_in[8];
    const float* bo = (const float*)d_in[9];
    const float* Wn = (const float*)d_in[10];
    const float* bn = (const float*)d_in[11];
    float* out = (float*)d_out;

    cudaFuncSetAttribute(k_projT,  cudaFuncAttributeMaxDynamicSharedMemorySize, PJ_SMEM);
    cudaFuncSetAttribute(k_fusedT, cudaFuncAttributeMaxDynamicSharedMemorySize, FS_SMEM);

    k_projT<<<PJ_BLOCKS, 256, PJ_SMEM>>>(nf, Wo, Wn);
    k_fusedT<<<296, 256, FS_SMEM>>>(ef, si, We, be, Wa, ba, wa, Wo, bo, Wn, bn, out);
}

// round 7
// speedup vs baseline: 1.9585x; 1.0428x over previous
#include <cuda_runtime.h>
#include <cuda_fp16.h>
#include <cstdint>
#include <cstddef>

#define N_SRC   100000
#define N_DST   50000
#define NODE_IN 128
#define HID     64
#define NTILE   (N_DST / 8)

__device__ float g_P[(size_t)N_SRC * HID];
__device__ float g_R[(size_t)N_DST * HID];

// ---------------------------------------------------------------------------
__device__ __forceinline__ uint32_t smem_u32(const void* p) {
    uint32_t a;
    asm("{ .reg .u64 t; cvta.to.shared.u64 t, %1; cvt.u32.u64 %0, t; }" : "=r"(a) : "l"(p));
    return a;
}
__device__ __forceinline__ void ldsm4(uint32_t r[4], uint32_t addr) {
    asm volatile("ldmatrix.sync.aligned.m8n8.x4.shared.b16 {%0,%1,%2,%3}, [%4];"
        : "=r"(r[0]), "=r"(r[1]), "=r"(r[2]), "=r"(r[3]) : "r"(addr));
}
__device__ __forceinline__ void mma_f16(float d[4], const uint32_t a[4],
                                        uint32_t b0, uint32_t b1) {
    asm volatile("mma.sync.aligned.m16n8k16.row.col.f32.f16.f16.f32 "
        "{%0,%1,%2,%3}, {%4,%5,%6,%7}, {%8,%9}, {%0,%1,%2,%3};"
        : "+f"(d[0]), "+f"(d[1]), "+f"(d[2]), "+f"(d[3])
        : "r"(a[0]), "r"(a[1]), "r"(a[2]), "r"(a[3]), "r"(b0), "r"(b1));
}
__device__ __forceinline__ void split2h(float a, float b, __half2& h, __half2& l) {
    h = __floats2half2_rn(a, b);
    const float2 f = __half22float2(h);
    l = __floats2half2_rn(a - f.x, b - f.y);
}
__device__ __forceinline__ uint32_t h2u(__half2 v) { return *(uint32_t*)&v; }

// 2-pass fp16 GEMM: A = hi+lo split, B single fp16
template<int KSTEPS, int STRIDE>
__device__ __forceinline__ void gemm_2p(uint32_t aH, uint32_t aL, uint32_t bS,
                                        int mrow, int ncol, int lane,
                                        float acc[2][4][4]) {
    const int arow = mrow + (lane & 15);
    const int asel = (lane >> 4) * 8;
    const int brow = ncol + ((lane >> 4) << 3) + (lane & 7);
    const int bsel = ((lane >> 3) & 1) * 8;
    #pragma unroll
    for (int ks = 0; ks < KSTEPS; ks++) {
        uint32_t ah[2][4], al[2][4], bs[2][4];
        #pragma unroll
        for (int mt = 0; mt < 2; mt++) {
            const uint32_t off = (uint32_t)(((arow + mt * 16) * STRIDE + ks * 16 + asel) * 2);
            ldsm4(ah[mt], aH + off);
            ldsm4(al[mt], aL + off);
        }
        #pragma unroll
        for (int j = 0; j < 2; j++) {
            const uint32_t off = (uint32_t)(((brow + j * 16) * STRIDE + ks * 16 + bsel) * 2);
            ldsm4(bs[j], bS + off);
        }
        #pragma unroll
        for (int mt = 0; mt < 2; mt++)
            #pragma unroll
            for (int nt = 0; nt < 4; nt++) {
                const int j = nt >> 1, hf = (nt & 1) * 2;
                mma_f16(acc[mt][nt], ah[mt], bs[j][hf], bs[j][hf + 1]);
                mma_f16(acc[mt][nt], al[mt], bs[j][hf], bs[j][hf + 1]);
            }
    }
}

// 1-pass fp16 GEMM: A single fp16, B single fp16
template<int KSTEPS, int STRIDE>
__device__ __forceinline__ void gemm_1p(uint32_t aS, uint32_t bS,
                                        int mrow, int ncol, int lane,
                                        float acc[2][4][4]) {
    const int arow = mrow + (lane & 15);
    const int asel = (lane >> 4) * 8;
    const int brow = ncol + ((lane >> 4) << 3) + (lane & 7);
    const int bsel = ((lane >> 3) & 1) * 8;
    #pragma unroll
    for (int ks = 0; ks < KSTEPS; ks++) {
        uint32_t ah[2][4], bs[2][4];
        #pragma unroll
        for (int mt = 0; mt < 2; mt++) {
            const uint32_t off = (uint32_t)(((arow + mt * 16) * STRIDE + ks * 16 + asel) * 2);
            ldsm4(ah[mt], aS + off);
        }
        #pragma unroll
        for (int j = 0; j < 2; j++) {
            const uint32_t off = (uint32_t)(((brow + j * 16) * STRIDE + ks * 16 + bsel) * 2);
            ldsm4(bs[j], bS + off);
        }
        #pragma unroll
        for (int mt = 0; mt < 2; mt++)
            #pragma unroll
            for (int nt = 0; nt < 4; nt++) {
                const int j = nt >> 1, hf = (nt & 1) * 2;
                mma_f16(acc[mt][nt], ah[mt], bs[j][hf], bs[j][hf + 1]);
            }
    }
}

// ---------------------------------------------------------------------------
// Kernel 1: P = nf @ Wo_top, R = nf[:N_DST] @ Wn_top
// ---------------------------------------------------------------------------
#define POFF_AH 0
#define POFF_AL 34816
#define POFF_W  69632
#define PJ_SMEM 87040
#define PJ_BLOCKS 296
#define PJ_PSPLIT 197

__global__ __launch_bounds__(256, 2)
void k_projT(const float* __restrict__ nf,
             const float* __restrict__ Wo,
             const float* __restrict__ Wn)
{
    extern __shared__ char smc[];
    const int tid = threadIdx.x, lane = tid & 31, wid = tid >> 5;
    const int mrow = (wid & 3) * 32, ncol = (wid >> 2) * 32;

    const bool isP = (blockIdx.x < PJ_PSPLIT);
    const float* W = isP ? Wo : Wn;
    float* dst = isP ? g_P : g_R;
    const int limit = isP ? N_SRC : N_DST;
    const int ntile = (limit + 127) >> 7;
    const int t0 = isP ? blockIdx.x : (blockIdx.x - PJ_PSPLIT);
    const int ts = isP ? PJ_PSPLIT : (PJ_BLOCKS - PJ_PSPLIT);

    for (int i = tid; i < 64 * 128; i += 256) {
        const int n = i >> 7, k = i & 127;
        ((__half*)(smc + POFF_W))[n * 136 + k] = __float2half(W[k * 64 + n]);
    }
    const uint32_t aH = smem_u32(smc + POFF_AH), aL = smem_u32(smc + POFF_AL);
    const uint32_t bS = smem_u32(smc + POFF_W);

    for (int tile = t0; tile < ntile; tile += ts) {
        __syncthreads();
        const int base = tile * 128;
        #pragma unroll
        for (int t = 0; t < 16; t++) {
            const int idx = tid + 256 * t;
            const int r = idx >> 5, q = idx & 31;
            float4 v = make_float4(0.f, 0.f, 0.f, 0.f);
            if (base + r < limit)
                v = ((const float4*)(nf + (size_t)(base + r) * NODE_IN))[q];
            __half2 h0, l0, h1, l1;
            split2h(v.x, v.y, h0, l0);
            split2h(v.z, v.w, h1, l1);
            const size_t bo_ = (size_t)(r * 136 + 4 * q) * 2;
            *(uint2*)(smc + POFF_AH + bo_) = make_uint2(h2u(h0), h2u(h1));
            *(uint2*)(smc + POFF_AL + bo_) = make_uint2(h2u(l0), h2u(l1));
        }
        __syncthreads();

        float acc[2][4][4];
        #pragma unroll
        for (int a = 0; a < 2; a++)
            #pragma unroll
            for (int b = 0; b < 4; b++)
                #pragma unroll
                for (int c = 0; c < 4; c++) acc[a][b][c] = 0.f;

        gemm_2p<8, 136>(aH, aL, bS, mrow, ncol, lane, acc);

        #pragma unroll
        for (int mt = 0; mt < 2; mt++) {
            const int r0 = base + mrow + mt * 16 + (lane >> 2);
            #pragma unroll
            for (int nt = 0; nt < 4; nt++) {
                const int c = ncol + nt * 8 + (lane & 3) * 2;
                if (r0 < limit)
                    *(float2*)(dst + (size_t)r0 * HID + c) =
                        make_float2(acc[mt][nt][0], acc[mt][nt][1]);
                if (r0 + 8 < limit)
                    *(float2*)(dst + (size_t)(r0 + 8) * HID + c) =
                        make_float2(acc[mt][nt][2], acc[mt][nt][3]);
            }
        }
    }
}

// ---------------------------------------------------------------------------
// Kernel 2: fused pipeline (E hi/lo; e_out SINGLE fp16; weights single)
// ---------------------------------------------------------------------------
#define OFF_EH   0
#define OFF_EL   18432
#define OFF_W1   36864
#define OFF_W2   46080
#define OFF_W3   55296
#define OFF_HNH  64512   // 16 x 72 fp16 (rows 8..15 stay zero)
#define OFF_HNL  66816
#define OFF_LOG  69120   // 128 floats
#define OFF_TAU  69632
#define OFF_AMX  69664
#define OFF_V    69696
#define OFF_BE   69952
#define OFF_BO   70208
#define OFF_BN   70464
#define OFF_SRC  70720
#define OFF_C    71232
#define FS_SMEM  71248

__global__ __launch_bounds__(256, 2)
void k_fusedT(const float* __restrict__ ef,
              const int*   __restrict__ src_idx,
              const float* __restrict__ We,  const float* __restrict__ be,
              const float* __restrict__ Wa,  const float* __restrict__ ba,
              const float* __restrict__ wa,
              const float* __restrict__ Wo,  const float* __restrict__ bo,
              const float* __restrict__ Wn,  const float* __restrict__ bn,
              float* __restrict__ out)
{
    extern __shared__ char smc[];
    const int tid = threadIdx.x, lane = tid & 31, wid = tid >> 5;
    const int mrow = (wid & 3) * 32, ncol = (wid >> 2) * 32;

    float* sLog = (float*)(smc + OFF_LOG);
    float* sTau = (float*)(smc + OFF_TAU);
    float* sAmx = (float*)(smc + OFF_AMX);
    float* sV   = (float*)(smc + OFF_V);
    float* sBe  = (float*)(smc + OFF_BE);
    float* sBo  = (float*)(smc + OFF_BO);
    float* sBn  = (float*)(smc + OFF_BN);
    int*   sSrc = (int*)  (smc + OFF_SRC);

    for (int i = tid; i < 4096; i += 256) {
        const int n = i >> 6, k = i & 63;
        ((__half*)(smc + OFF_W1))[n * 72 + k] = __float2half(We[k * 64 + n]);
        ((__half*)(smc + OFF_W2))[n * 72 + k] = __float2half(Wo[(NODE_IN + k) * 64 + n]);
        ((__half*)(smc + OFF_W3))[n * 72 + k] = __float2half(Wn[(NODE_IN + k) * 64 + n]);
    }
    for (int i = tid; i < 288; i += 256) {
        ((uint32_t*)(smc + OFF_HNH + 1152))[i] = 0;
        ((uint32_t*)(smc + OFF_HNL + 1152))[i] = 0;
    }
    if (tid < 64) {
        sBe[tid] = be[tid]; sBo[tid] = bo[tid]; sBn[tid] = bn[tid];
        float sv = 0.f;
        #pragma unroll 8
        for (int k = 0; k < 64; k++) sv = fmaf(Wa[tid * 64 + k], wa[k], sv);
        sV[tid] = sv;
    }
    if (tid == 64) {
        float sc = 0.f;
        for (int k = 0; k < 64; k++) sc = fmaf(ba[k], wa[k], sc);
        *(float*)(smc + OFF_C) = sc;
    }
    __syncthreads();
    const float cval = *(const float*)(smc + OFF_C);

    const uint32_t eH = smem_u32(smc + OFF_EH), eL = smem_u32(smc + OFF_EL);
    const uint32_t w1 = smem_u32(smc + OFF_W1), w2 = smem_u32(smc + OFF_W2);
    const uint32_t w3 = smem_u32(smc + OFF_W3);
    const uint32_t hnH = smem_u32(smc + OFF_HNH), hnL = smem_u32(smc + OFF_HNL);

    // hoist GEMM3 B fragments (loop-invariant)
    uint32_t b3[2][4];
    {
        const int nc = wid * 8;
        #pragma unroll
        for (int g = 0; g < 2; g++) {
            const uint32_t off = (uint32_t)(((nc + (lane & 7)) * 72 + (lane >> 3) * 8 + g * 32) * 2);
            ldsm4(b3[g], w3 + off);
        }
    }

    for (int tile = blockIdx.x; tile < NTILE; tile += gridDim.x) {
        __syncthreads();

        // ---- stage E tile -> hi/lo fp16 + fused fp32 logits ----
        const float4* eg = (const float4*)(ef + (size_t)tile * 8192);
        #pragma unroll
        for (int t = 0; t < 8; t++) {
            const int idx = tid + 256 * t;
            const int r = idx >> 4, q = idx & 15;
            const float4 v = eg[idx];
            __half2 h0, l0, h1, l1;
            split2h(v.x, v.y, h0, l0);
            split2h(v.z, v.w, h1, l1);
            const size_t bo_ = (size_t)(r * 72 + 4 * q) * 2;
            *(uint2*)(smc + OFF_EH + bo_) = make_uint2(h2u(h0), h2u(h1));
            *(uint2*)(smc + OFF_EL + bo_) = make_uint2(h2u(l0), h2u(l1));
            float p = v.x * sV[4 * q] + v.y * sV[4 * q + 1]
                    + v.z * sV[4 * q + 2] + v.w * sV[4 * q + 3];
            p += __shfl_xor_sync(0xffffffffu, p, 1);
            p += __shfl_xor_sync(0xffffffffu, p, 2);
            p += __shfl_xor_sync(0xffffffffu, p, 4);
            p += __shfl_xor_sync(0xffffffffu, p, 8);
            if ((tid & 15) == 0) sLog[r] = p;
        }
        if (tid < 128) sSrc[tid] = src_idx[tile * 128 + tid];
        __syncthreads();

        // ---- sparsemax (8 threads) ----
        if (tid < 8) {
            float z[16], amax = -3.4e38f;
            #pragma unroll
            for (int d = 0; d < 16; d++) {
                float raw = sLog[tid * 16 + d] + cval;
                raw = (raw > 0.f) ? raw : 0.01f * raw;
                sLog[tid * 16 + d] = raw;
                z[d] = raw; amax = fmaxf(amax, z[d]);
            }
            #pragma unroll
            for (int d = 0; d < 16; d++) z[d] -= amax;
            #pragma unroll
            for (int kk2 = 2; kk2 <= 16; kk2 <<= 1)
                #pragma unroll
                for (int j = kk2 >> 1; j > 0; j >>= 1)
                    #pragma unroll
                    for (int i = 0; i < 16; i++) {
                        const int l = i ^ j;
                        if (l > i) {
                            const bool up = ((i & kk2) == 0);
                            const float a0 = z[i], b0 = z[l];
                            if (up ? (a0 > b0) : (a0 < b0)) { z[i] = b0; z[l] = a0; }
                        }
                    }
            float cs = 0.f, cssel = 0.f, kk = 1.f;
            #pragma unroll
            for (int j = 1; j <= 16; j++) {
                const float zz = z[16 - j];
                cs += zz;
                if (1.f + (float)j * zz > cs) { kk = (float)j; cssel = cs; }
            }
            sTau[tid] = (cssel - 1.f) / kk;
            sAmx[tid] = amax;
        }

        float acc[2][4][4];

        // ---- GEMM1: e_out_pre = E @ We^T  (A hi/lo, 2-pass) ----
        #pragma unroll
        for (int a = 0; a < 2; a++)
            #pragma unroll
            for (int b = 0; b < 4; b++)
                #pragma unroll
                for (int c = 0; c < 4; c++) acc[a][b][c] = 0.f;
        gemm_2p<4, 72>(eH, eL, w1, mrow, ncol, lane, acc);
        __syncthreads();

        // ---- epilogue1: relu(+be) -> SINGLE fp16 into E-hi buffer ----
        #pragma unroll
        for (int mt = 0; mt < 2; mt++) {
            const int r0 = mrow + mt * 16 + (lane >> 2);
            #pragma unroll
            for (int nt = 0; nt < 4; nt++) {
                const int c = ncol + nt * 8 + (lane & 3) * 2;
                const float x0 = fmaxf(acc[mt][nt][0] + sBe[c],     0.f);
                const float x1 = fmaxf(acc[mt][nt][1] + sBe[c + 1], 0.f);
                const float x2 = fmaxf(acc[mt][nt][2] + sBe[c],     0.f);
                const float x3 = fmaxf(acc[mt][nt][3] + sBe[c + 1], 0.f);
                *(uint32_t*)(smc + OFF_EH + (size_t)(r0 * 72 + c) * 2) =
                    h2u(__floats2half2_rn(x0, x1));
                *(uint32_t*)(smc + OFF_EH + (size_t)((r0 + 8) * 72 + c) * 2) =
                    h2u(__floats2half2_rn(x2, x3));
            }
        }
        __syncthreads();

        // ---- GEMM2: m_pre = e_out @ Wo_bot^T  (A single, 1-pass) ----
        #pragma unroll
        for (int a = 0; a < 2; a++)
            #pragma unroll
            for (int b = 0; b < 4; b++)
                #pragma unroll
                for (int c = 0; c < 4; c++) acc[a][b][c] = 0.f;
        gemm_1p<4, 72>(eH, w2, mrow, ncol, lane, acc);

        // ---- epilogue2: m = relu(m_pre + P[src] + bo); alpha-weighted sum ----
        #pragma unroll
        for (int mt = 0; mt < 2; mt++) {
            const int ln = (mrow >> 4) + mt;
            const int r0 = mrow + mt * 16 + (lane >> 2);
            const int r1 = r0 + 8;
            const int s0 = sSrc[r0], s1 = sSrc[r1];
            const float at = sAmx[ln] + sTau[ln];
            const float al0 = fmaxf(sLog[r0] - at, 0.f);
            const float al1 = fmaxf(sLog[r1] - at, 0.f);
            #pragma unroll
            for (int nt = 0; nt < 4; nt++) {
                const int c = ncol + nt * 8 + (lane & 3) * 2;
                const float2 p0 = *(const float2*)(g_P + (size_t)s0 * HID + c);
                const float2 p1 = *(const float2*)(g_P + (size_t)s1 * HID + c);
                const float m00 = fmaxf(acc[mt][nt][0] + p0.x + sBo[c],     0.f);
                const float m01 = fmaxf(acc[mt][nt][1] + p0.y + sBo[c + 1], 0.f);
                const float m10 = fmaxf(acc[mt][nt][2] + p1.x + sBo[c],     0.f);
                const float m11 = fmaxf(acc[mt][nt][3] + p1.y + sBo[c + 1], 0.f);
                float sx = m00 * al0 + m10 * al1;
                float sy = m01 * al0 + m11 * al1;
                sx += __shfl_xor_sync(0xffffffffu, sx, 4);
                sy += __shfl_xor_sync(0xffffffffu, sy, 4);
                sx += __shfl_xor_sync(0xffffffffu, sx, 8);
                sy += __shfl_xor_sync(0xffffffffu, sy, 8);
                sx += __shfl_xor_sync(0xffffffffu, sx, 16);
                sy += __shfl_xor_sync(0xffffffffu, sy, 16);
                if (lane < 4) {
                    __half2 hh, ll;
                    split2h(sx, sy, hh, ll);
                    *(uint32_t*)(smc + OFF_HNH + (size_t)(ln * 72 + c) * 2) = h2u(hh);
                    *(uint32_t*)(smc + OFF_HNL + (size_t)(ln * 72 + c) * 2) = h2u(ll);
                }
            }
        }
        __syncthreads();

        // ---- GEMM3 (MMA, M=16 padded): out = relu(R + HN @ Wn_bot^T + bn) ----
        {
            float acc3[4] = {0.f, 0.f, 0.f, 0.f};
            #pragma unroll
            for (int ks = 0; ks < 4; ks++) {
                uint32_t a3h[4], a3l[4];
                const uint32_t aoff = (uint32_t)(((lane & 15) * 72 + ks * 16 + (lane >> 4) * 8) * 2);
                ldsm4(a3h, hnH + aoff);
                ldsm4(a3l, hnL + aoff);
                const int g = ks >> 1, pr = (ks & 1) * 2;
                mma_f16(acc3, a3h, b3[g][pr], b3[g][pr + 1]);
                mma_f16(acc3, a3l, b3[g][pr], b3[g][pr + 1]);
            }
            const int node = tile * 8 + (lane >> 2);
            const int col = wid * 8 + (lane & 3) * 2;
            const float2 r2 = *(const float2*)(g_R + (size_t)node * HID + col);
            const float o0 = acc3[0] + r2.x + sBn[col];
            const float o1 = acc3[1] + r2.y + sBn[col + 1];
            *(float2*)(out + (size_t)node * HID + col) =
                make_float2(fmaxf(o0, 0.f), fmaxf(o1, 0.f));
        }
    }
}

// ---------------------------------------------------------------------------
extern "C" void kernel_launch(void* const* d_in, const int* in_sizes, int n_in,
                              void* d_out, int out_size)
{
    const float* nf = (const float*)d_in[0];
    const float* ef = (const float*)d_in[1];
    const int*   si = (const int*)  d_in[2];
    const float* We = (const float*)d_in[3];
    const float* be = (const float*)d_in[4];
    const float* Wa = (const float*)d_in[5];
    const float* ba = (const float*)d_in[6];
    const float* wa = (const float*)d_in[7];
    const float* Wo = (const float*)d_in[8];
    const float* bo = (const float*)d_in[9];
    const float* Wn = (const float*)d_in[10];
    const float* bn = (const float*)d_in[11];
    float* out = (float*)d_out;

    cudaFuncSetAttribute(k_projT,  cudaFuncAttributeMaxDynamicSharedMemorySize, PJ_SMEM);
    cudaFuncSetAttribute(k_fusedT, cudaFuncAttributeMaxDynamicSharedMemorySize, FS_SMEM);

    k_projT<<<PJ_BLOCKS, 256, PJ_SMEM>>>(nf, Wo, Wn);
    k_fusedT<<<296, 256, FS_SMEM>>>(ef, si, We, be, Wa, ba, wa, Wo, bo, Wn, bn, out);
}

// round 8
// speedup vs baseline: 2.0967x; 1.0706x over previous
#include <cuda_runtime.h>
#include <cuda_fp16.h>
#include <cstdint>
#include <cstddef>

#define N_SRC   100000
#define N_DST   50000
#define NODE_IN 128
#define HID     64
#define NTILE   (N_DST / 8)

__device__ __half g_P[(size_t)N_SRC * HID];   // fp16 storage (12.8 MB, L2-resident)
__device__ float  g_R[(size_t)N_DST * HID];

// ---------------------------------------------------------------------------
__device__ __forceinline__ uint32_t smem_u32(const void* p) {
    uint32_t a;
    asm("{ .reg .u64 t; cvta.to.shared.u64 t, %1; cvt.u32.u64 %0, t; }" : "=r"(a) : "l"(p));
    return a;
}
__device__ __forceinline__ void ldsm4(uint32_t r[4], uint32_t addr) {
    asm volatile("ldmatrix.sync.aligned.m8n8.x4.shared.b16 {%0,%1,%2,%3}, [%4];"
        : "=r"(r[0]), "=r"(r[1]), "=r"(r[2]), "=r"(r[3]) : "r"(addr));
}
__device__ __forceinline__ void mma_f16(float d[4], const uint32_t a[4],
                                        uint32_t b0, uint32_t b1) {
    asm volatile("mma.sync.aligned.m16n8k16.row.col.f32.f16.f16.f32 "
        "{%0,%1,%2,%3}, {%4,%5,%6,%7}, {%8,%9}, {%0,%1,%2,%3};"
        : "+f"(d[0]), "+f"(d[1]), "+f"(d[2]), "+f"(d[3])
        : "r"(a[0]), "r"(a[1]), "r"(a[2]), "r"(a[3]), "r"(b0), "r"(b1));
}
__device__ __forceinline__ void split2h(float a, float b, __half2& h, __half2& l) {
    h = __floats2half2_rn(a, b);
    const float2 f = __half22float2(h);
    l = __floats2half2_rn(a - f.x, b - f.y);
}
__device__ __forceinline__ uint32_t h2u(__half2 v) { return *(uint32_t*)&v; }

// 2-pass fp16 GEMM (A hi/lo split, B single) — used by k_projT for precision
template<int KSTEPS, int STRIDE>
__device__ __forceinline__ void gemm_2p(uint32_t aH, uint32_t aL, uint32_t bS,
                                        int mrow, int ncol, int lane,
                                        float acc[2][4][4]) {
    const int arow = mrow + (lane & 15);
    const int asel = (lane >> 4) * 8;
    const int brow = ncol + ((lane >> 4) << 3) + (lane & 7);
    const int bsel = ((lane >> 3) & 1) * 8;
    #pragma unroll
    for (int ks = 0; ks < KSTEPS; ks++) {
        uint32_t ah[2][4], al[2][4], bs[2][4];
        #pragma unroll
        for (int mt = 0; mt < 2; mt++) {
            const uint32_t off = (uint32_t)(((arow + mt * 16) * STRIDE + ks * 16 + asel) * 2);
            ldsm4(ah[mt], aH + off);
            ldsm4(al[mt], aL + off);
        }
        #pragma unroll
        for (int j = 0; j < 2; j++) {
            const uint32_t off = (uint32_t)(((brow + j * 16) * STRIDE + ks * 16 + bsel) * 2);
            ldsm4(bs[j], bS + off);
        }
        #pragma unroll
        for (int mt = 0; mt < 2; mt++)
            #pragma unroll
            for (int nt = 0; nt < 4; nt++) {
                const int j = nt >> 1, hf = (nt & 1) * 2;
                mma_f16(acc[mt][nt], ah[mt], bs[j][hf], bs[j][hf + 1]);
                mma_f16(acc[mt][nt], al[mt], bs[j][hf], bs[j][hf + 1]);
            }
    }
}

// 1-pass fp16 GEMM (A single, B single)
template<int KSTEPS, int STRIDE>
__device__ __forceinline__ void gemm_1p(uint32_t aS, uint32_t bS,
                                        int mrow, int ncol, int lane,
                                        float acc[2][4][4]) {
    const int arow = mrow + (lane & 15);
    const int asel = (lane >> 4) * 8;
    const int brow = ncol + ((lane >> 4) << 3) + (lane & 7);
    const int bsel = ((lane >> 3) & 1) * 8;
    #pragma unroll
    for (int ks = 0; ks < KSTEPS; ks++) {
        uint32_t ah[2][4], bs[2][4];
        #pragma unroll
        for (int mt = 0; mt < 2; mt++) {
            const uint32_t off = (uint32_t)(((arow + mt * 16) * STRIDE + ks * 16 + asel) * 2);
            ldsm4(ah[mt], aS + off);
        }
        #pragma unroll
        for (int j = 0; j < 2; j++) {
            const uint32_t off = (uint32_t)(((brow + j * 16) * STRIDE + ks * 16 + bsel) * 2);
            ldsm4(bs[j], bS + off);
        }
        #pragma unroll
        for (int mt = 0; mt < 2; mt++)
            #pragma unroll
            for (int nt = 0; nt < 4; nt++) {
                const int j = nt >> 1, hf = (nt & 1) * 2;
                mma_f16(acc[mt][nt], ah[mt], bs[j][hf], bs[j][hf + 1]);
            }
    }
}

// ---------------------------------------------------------------------------
// Kernel 1: P(fp16) = nf @ Wo_top, R(fp32) = nf[:N_DST] @ Wn_top
// ---------------------------------------------------------------------------
#define POFF_AH 0
#define POFF_AL 34816
#define POFF_W  69632
#define PJ_SMEM 87040
#define PJ_BLOCKS 296
#define PJ_PSPLIT 197

__global__ __launch_bounds__(256, 2)
void k_projT(const float* __restrict__ nf,
             const float* __restrict__ Wo,
             const float* __restrict__ Wn)
{
    extern __shared__ char smc[];
    const int tid = threadIdx.x, lane = tid & 31, wid = tid >> 5;
    const int mrow = (wid & 3) * 32, ncol = (wid >> 2) * 32;

    const bool isP = (blockIdx.x < PJ_PSPLIT);
    const float* W = isP ? Wo : Wn;
    const int limit = isP ? N_SRC : N_DST;
    const int ntile = (limit + 127) >> 7;
    const int t0 = isP ? blockIdx.x : (blockIdx.x - PJ_PSPLIT);
    const int ts = isP ? PJ_PSPLIT : (PJ_BLOCKS - PJ_PSPLIT);

    for (int i = tid; i < 64 * 128; i += 256) {
        const int n = i >> 7, k = i & 127;
        ((__half*)(smc + POFF_W))[n * 136 + k] = __float2half(W[k * 64 + n]);
    }
    const uint32_t aH = smem_u32(smc + POFF_AH), aL = smem_u32(smc + POFF_AL);
    const uint32_t bS = smem_u32(smc + POFF_W);

    for (int tile = t0; tile < ntile; tile += ts) {
        __syncthreads();
        const int base = tile * 128;
        #pragma unroll
        for (int t = 0; t < 16; t++) {
            const int idx = tid + 256 * t;
            const int r = idx >> 5, q = idx & 31;
            float4 v = make_float4(0.f, 0.f, 0.f, 0.f);
            if (base + r < limit)
                v = ((const float4*)(nf + (size_t)(base + r) * NODE_IN))[q];
            __half2 h0, l0, h1, l1;
            split2h(v.x, v.y, h0, l0);
            split2h(v.z, v.w, h1, l1);
            const size_t bo_ = (size_t)(r * 136 + 4 * q) * 2;
            *(uint2*)(smc + POFF_AH + bo_) = make_uint2(h2u(h0), h2u(h1));
            *(uint2*)(smc + POFF_AL + bo_) = make_uint2(h2u(l0), h2u(l1));
        }
        __syncthreads();

        float acc[2][4][4];
        #pragma unroll
        for (int a = 0; a < 2; a++)
            #pragma unroll
            for (int b = 0; b < 4; b++)
                #pragma unroll
                for (int c = 0; c < 4; c++) acc[a][b][c] = 0.f;

        gemm_2p<8, 136>(aH, aL, bS, mrow, ncol, lane, acc);

        #pragma unroll
        for (int mt = 0; mt < 2; mt++) {
            const int r0 = base + mrow + mt * 16 + (lane >> 2);
            #pragma unroll
            for (int nt = 0; nt < 4; nt++) {
                const int c = ncol + nt * 8 + (lane & 3) * 2;
                if (isP) {
                    if (r0 < limit)
                        *(uint32_t*)(g_P + (size_t)r0 * HID + c) =
                            h2u(__floats2half2_rn(acc[mt][nt][0], acc[mt][nt][1]));
                    if (r0 + 8 < limit)
                        *(uint32_t*)(g_P + (size_t)(r0 + 8) * HID + c) =
                            h2u(__floats2half2_rn(acc[mt][nt][2], acc[mt][nt][3]));
                } else {
                    if (r0 < limit)
                        *(float2*)(g_R + (size_t)r0 * HID + c) =
                            make_float2(acc[mt][nt][0], acc[mt][nt][1]);
                    if (r0 + 8 < limit)
                        *(float2*)(g_R + (size_t)(r0 + 8) * HID + c) =
                            make_float2(acc[mt][nt][2], acc[mt][nt][3]);
                }
            }
        }
    }
}

// ---------------------------------------------------------------------------
// Kernel 2: fused pipeline (E single fp16; e_out single; P fp16 gather)
// ---------------------------------------------------------------------------
#define OFF_EH   0        // 18432: E tile single fp16 (stride 72)
#define OFF_W1   18432
#define OFF_W2   27648
#define OFF_W3   36864
#define OFF_HNH  46080    // 16 x 72 fp16 (rows 8..15 stay zero)
#define OFF_HNL  48384
#define OFF_LOG  50688    // 128 floats
#define OFF_TAU  51200
#define OFF_AMX  51232
#define OFF_V    51264
#define OFF_BE   51520
#define OFF_BO   51776
#define OFF_BN   52032
#define OFF_SRC  52288
#define OFF_C    52800
#define FS_SMEM  52816

__global__ __launch_bounds__(256, 2)
void k_fusedT(const float* __restrict__ ef,
              const int*   __restrict__ src_idx,
              const float* __restrict__ We,  const float* __restrict__ be,
              const float* __restrict__ Wa,  const float* __restrict__ ba,
              const float* __restrict__ wa,
              const float* __restrict__ Wo,  const float* __restrict__ bo,
              const float* __restrict__ Wn,  const float* __restrict__ bn,
              float* __restrict__ out)
{
    extern __shared__ char smc[];
    const int tid = threadIdx.x, lane = tid & 31, wid = tid >> 5;
    const int mrow = (wid & 3) * 32, ncol = (wid >> 2) * 32;

    float* sLog = (float*)(smc + OFF_LOG);
    float* sTau = (float*)(smc + OFF_TAU);
    float* sAmx = (float*)(smc + OFF_AMX);
    float* sV   = (float*)(smc + OFF_V);
    float* sBe  = (float*)(smc + OFF_BE);
    float* sBo  = (float*)(smc + OFF_BO);
    float* sBn  = (float*)(smc + OFF_BN);
    int*   sSrc = (int*)  (smc + OFF_SRC);

    for (int i = tid; i < 4096; i += 256) {
        const int n = i >> 6, k = i & 63;
        ((__half*)(smc + OFF_W1))[n * 72 + k] = __float2half(We[k * 64 + n]);
        ((__half*)(smc + OFF_W2))[n * 72 + k] = __float2half(Wo[(NODE_IN + k) * 64 + n]);
        ((__half*)(smc + OFF_W3))[n * 72 + k] = __float2half(Wn[(NODE_IN + k) * 64 + n]);
    }
    for (int i = tid; i < 288; i += 256) {
        ((uint32_t*)(smc + OFF_HNH + 1152))[i] = 0;
        ((uint32_t*)(smc + OFF_HNL + 1152))[i] = 0;
    }
    if (tid < 64) {
        sBe[tid] = be[tid]; sBo[tid] = bo[tid]; sBn[tid] = bn[tid];
        float sv = 0.f;
        #pragma unroll 8
        for (int k = 0; k < 64; k++) sv = fmaf(Wa[tid * 64 + k], wa[k], sv);
        sV[tid] = sv;
    }
    if (tid == 64) {
        float sc = 0.f;
        for (int k = 0; k < 64; k++) sc = fmaf(ba[k], wa[k], sc);
        *(float*)(smc + OFF_C) = sc;
    }
    __syncthreads();
    const float cval = *(const float*)(smc + OFF_C);

    const uint32_t eH = smem_u32(smc + OFF_EH);
    const uint32_t w1 = smem_u32(smc + OFF_W1), w2 = smem_u32(smc + OFF_W2);
    const uint32_t w3 = smem_u32(smc + OFF_W3);
    const uint32_t hnH = smem_u32(smc + OFF_HNH), hnL = smem_u32(smc + OFF_HNL);

    // hoist GEMM3 B fragments (loop-invariant)
    uint32_t b3[2][4];
    {
        const int nc = wid * 8;
        #pragma unroll
        for (int g = 0; g < 2; g++) {
            const uint32_t off = (uint32_t)(((nc + (lane & 7)) * 72 + (lane >> 3) * 8 + g * 32) * 2);
            ldsm4(b3[g], w3 + off);
        }
    }

    for (int tile = blockIdx.x; tile < NTILE; tile += gridDim.x) {
        __syncthreads();

        // ---- stage E tile -> single fp16 + fused fp32 logits ----
        const float4* eg = (const float4*)(ef + (size_t)tile * 8192);
        #pragma unroll
        for (int t = 0; t < 8; t++) {
            const int idx = tid + 256 * t;
            const int r = idx >> 4, q = idx & 15;
            const float4 v = eg[idx];
            const size_t bo_ = (size_t)(r * 72 + 4 * q) * 2;
            *(uint2*)(smc + OFF_EH + bo_) =
                make_uint2(h2u(__floats2half2_rn(v.x, v.y)),
                           h2u(__floats2half2_rn(v.z, v.w)));
            float p = v.x * sV[4 * q] + v.y * sV[4 * q + 1]
                    + v.z * sV[4 * q + 2] + v.w * sV[4 * q + 3];
            p += __shfl_xor_sync(0xffffffffu, p, 1);
            p += __shfl_xor_sync(0xffffffffu, p, 2);
            p += __shfl_xor_sync(0xffffffffu, p, 4);
            p += __shfl_xor_sync(0xffffffffu, p, 8);
            if ((tid & 15) == 0) sLog[r] = p;
        }
        if (tid < 128) sSrc[tid] = src_idx[tile * 128 + tid];
        __syncthreads();

        // ---- sparsemax (8 threads) — overlaps with GEMM1 on other warps ----
        if (tid < 8) {
            float z[16], amax = -3.4e38f;
            #pragma unroll
            for (int d = 0; d < 16; d++) {
                float raw = sLog[tid * 16 + d] + cval;
                raw = (raw > 0.f) ? raw : 0.01f * raw;
                sLog[tid * 16 + d] = raw;
                z[d] = raw; amax = fmaxf(amax, z[d]);
            }
            #pragma unroll
            for (int d = 0; d < 16; d++) z[d] -= amax;
            #pragma unroll
            for (int kk2 = 2; kk2 <= 16; kk2 <<= 1)
                #pragma unroll
                for (int j = kk2 >> 1; j > 0; j >>= 1)
                    #pragma unroll
                    for (int i = 0; i < 16; i++) {
                        const int l = i ^ j;
                        if (l > i) {
                            const bool up = ((i & kk2) == 0);
                            const float a0 = z[i], b0 = z[l];
                            if (up ? (a0 > b0) : (a0 < b0)) { z[i] = b0; z[l] = a0; }
                        }
                    }
            float cs = 0.f, cssel = 0.f, kk = 1.f;
            #pragma unroll
            for (int j = 1; j <= 16; j++) {
                const float zz = z[16 - j];
                cs += zz;
                if (1.f + (float)j * zz > cs) { kk = (float)j; cssel = cs; }
            }
            sTau[tid] = (cssel - 1.f) / kk;
            sAmx[tid] = amax;
        }

        float acc[2][4][4];

        // ---- GEMM1: e_out_pre = E @ We^T  (1-pass) ----
        #pragma unroll
        for (int a = 0; a < 2; a++)
            #pragma unroll
            for (int b = 0; b < 4; b++)
                #pragma unroll
                for (int c = 0; c < 4; c++) acc[a][b][c] = 0.f;
        gemm_1p<4, 72>(eH, w1, mrow, ncol, lane, acc);
        __syncthreads();

        // ---- epilogue1: relu(+be) -> single fp16 back into E buffer ----
        #pragma unroll
        for (int mt = 0; mt < 2; mt++) {
            const int r0 = mrow + mt * 16 + (lane >> 2);
            #pragma unroll
            for (int nt = 0; nt < 4; nt++) {
                const int c = ncol + nt * 8 + (lane & 3) * 2;
                const float x0 = fmaxf(acc[mt][nt][0] + sBe[c],     0.f);
                const float x1 = fmaxf(acc[mt][nt][1] + sBe[c + 1], 0.f);
                const float x2 = fmaxf(acc[mt][nt][2] + sBe[c],     0.f);
                const float x3 = fmaxf(acc[mt][nt][3] + sBe[c + 1], 0.f);
                *(uint32_t*)(smc + OFF_EH + (size_t)(r0 * 72 + c) * 2) =
                    h2u(__floats2half2_rn(x0, x1));
                *(uint32_t*)(smc + OFF_EH + (size_t)((r0 + 8) * 72 + c) * 2) =
                    h2u(__floats2half2_rn(x2, x3));
            }
        }
        __syncthreads();

        // ---- GEMM2: m_pre = e_out @ Wo_bot^T  (1-pass) ----
        #pragma unroll
        for (int a = 0; a < 2; a++)
            #pragma unroll
            for (int b = 0; b < 4; b++)
                #pragma unroll
                for (int c = 0; c < 4; c++) acc[a][b][c] = 0.f;
        gemm_1p<4, 72>(eH, w2, mrow, ncol, lane, acc);

        // ---- epilogue2: m = relu(m_pre + P[src] + bo); alpha-weighted sum ----
        #pragma unroll
        for (int mt = 0; mt < 2; mt++) {
            const int ln = (mrow >> 4) + mt;
            const int r0 = mrow + mt * 16 + (lane >> 2);
            const int r1 = r0 + 8;
            const int s0 = sSrc[r0], s1 = sSrc[r1];
            const float at = sAmx[ln] + sTau[ln];
            const float al0 = fmaxf(sLog[r0] - at, 0.f);
            const float al1 = fmaxf(sLog[r1] - at, 0.f);
            #pragma unroll
            for (int nt = 0; nt < 4; nt++) {
                const int c = ncol + nt * 8 + (lane & 3) * 2;
                const uint32_t pv0 = *(const uint32_t*)(g_P + (size_t)s0 * HID + c);
                const uint32_t pv1 = *(const uint32_t*)(g_P + (size_t)s1 * HID + c);
                const float2 p0 = __half22float2(*(const __half2*)&pv0);
                const float2 p1 = __half22float2(*(const __half2*)&pv1);
                const float m00 = fmaxf(acc[mt][nt][0] + p0.x + sBo[c],     0.f);
                const float m01 = fmaxf(acc[mt][nt][1] + p0.y + sBo[c + 1], 0.f);
                const float m10 = fmaxf(acc[mt][nt][2] + p1.x + sBo[c],     0.f);
                const float m11 = fmaxf(acc[mt][nt][3] + p1.y + sBo[c + 1], 0.f);
                float sx = m00 * al0 + m10 * al1;
                float sy = m01 * al0 + m11 * al1;
                sx += __shfl_xor_sync(0xffffffffu, sx, 4);
                sy += __shfl_xor_sync(0xffffffffu, sy, 4);
                sx += __shfl_xor_sync(0xffffffffu, sx, 8);
                sy += __shfl_xor_sync(0xffffffffu, sy, 8);
                sx += __shfl_xor_sync(0xffffffffu, sx, 16);
                sy += __shfl_xor_sync(0xffffffffu, sy, 16);
                if (lane < 4) {
                    __half2 hh, ll;
                    split2h(sx, sy, hh, ll);
                    *(uint32_t*)(smc + OFF_HNH + (size_t)(ln * 72 + c) * 2) = h2u(hh);
                    *(uint32_t*)(smc + OFF_HNL + (size_t)(ln * 72 + c) * 2) = h2u(ll);
                }
            }
        }
        __syncthreads();

        // ---- GEMM3 (MMA, M=16 padded): out = relu(R + HN @ Wn_bot^T + bn) ----
        {
            float acc3[4] = {0.f, 0.f, 0.f, 0.f};
            #pragma unroll
            for (int ks = 0; ks < 4; ks++) {
                uint32_t a3h[4], a3l[4];
                const uint32_t aoff = (uint32_t)(((lane & 15) * 72 + ks * 16 + (lane >> 4) * 8) * 2);
                ldsm4(a3h, hnH + aoff);
                ldsm4(a3l, hnL + aoff);
                const int g = ks >> 1, pr = (ks & 1) * 2;
                mma_f16(acc3, a3h, b3[g][pr], b3[g][pr + 1]);
                mma_f16(acc3, a3l, b3[g][pr], b3[g][pr + 1]);
            }
            const int node = tile * 8 + (lane >> 2);
            const int col = wid * 8 + (lane & 3) * 2;
            const float2 r2 = *(const float2*)(g_R + (size_t)node * HID + col);
            const float o0 = acc3[0] + r2.x + sBn[col];
            const float o1 = acc3[1] + r2.y + sBn[col + 1];
            *(float2*)(out + (size_t)node * HID + col) =
                make_float2(fmaxf(o0, 0.f), fmaxf(o1, 0.f));
        }
    }
}

// ---------------------------------------------------------------------------
extern "C" void kernel_launch(void* const* d_in, const int* in_sizes, int n_in,
                              void* d_out, int out_size)
{
    const float* nf = (const float*)d_in[0];
    const float* ef = (const float*)d_in[1];
    const int*   si = (const int*)  d_in[2];
    const float* We = (const float*)d_in[3];
    const float* be = (const float*)d_in[4];
    const float* Wa = (const float*)d_in[5];
    const float* ba = (const float*)d_in[6];
    const float* wa = (const float*)d_in[7];
    const float* Wo = (const float*)d_in[8];
    const float* bo = (const float*)d_in[9];
    const float* Wn = (const float*)d_in[10];
    const float* bn = (const float*)d_in[11];
    float* out = (float*)d_out;

    cudaFuncSetAttribute(k_projT,  cudaFuncAttributeMaxDynamicSharedMemorySize, PJ_SMEM);
    cudaFuncSetAttribute(k_fusedT, cudaFuncAttributeMaxDynamicSharedMemorySize, FS_SMEM);

    k_projT<<<PJ_BLOCKS, 256, PJ_SMEM>>>(nf, Wo, Wn);
    k_fusedT<<<296, 256, FS_SMEM>>>(ef, si, We, be, Wa, ba, wa, Wo, bo, Wn, bn, out);
}

// round 9
// speedup vs baseline: 2.2234x; 1.0604x over previous
#include <cuda_runtime.h>
#include <cuda_fp16.h>
#include <cstdint>
#include <cstddef>

#define N_SRC   100000
#define N_DST   50000
#define NODE_IN 128
#define HID     64
#define NTILE   (N_DST / 8)

__device__ __half g_P[(size_t)N_SRC * HID];   // fp16 storage (12.8 MB, L2-resident)
__device__ float  g_R[(size_t)N_DST * HID];

// ---------------------------------------------------------------------------
__device__ __forceinline__ uint32_t smem_u32(const void* p) {
    uint32_t a;
    asm("{ .reg .u64 t; cvta.to.shared.u64 t, %1; cvt.u32.u64 %0, t; }" : "=r"(a) : "l"(p));
    return a;
}
__device__ __forceinline__ void ldsm4(uint32_t r[4], uint32_t addr) {
    asm volatile("ldmatrix.sync.aligned.m8n8.x4.shared.b16 {%0,%1,%2,%3}, [%4];"
        : "=r"(r[0]), "=r"(r[1]), "=r"(r[2]), "=r"(r[3]) : "r"(addr));
}
__device__ __forceinline__ void mma_f16(float d[4], const uint32_t a[4],
                                        uint32_t b0, uint32_t b1) {
    asm volatile("mma.sync.aligned.m16n8k16.row.col.f32.f16.f16.f32 "
        "{%0,%1,%2,%3}, {%4,%5,%6,%7}, {%8,%9}, {%0,%1,%2,%3};"
        : "+f"(d[0]), "+f"(d[1]), "+f"(d[2]), "+f"(d[3])
        : "r"(a[0]), "r"(a[1]), "r"(a[2]), "r"(a[3]), "r"(b0), "r"(b1));
}
__device__ __forceinline__ uint32_t h2u(__half2 v) { return *(uint32_t*)&v; }

// 1-pass fp16 GEMM (A single, B single), warp tile 32x32
template<int KSTEPS, int STRIDE>
__device__ __forceinline__ void gemm_1p(uint32_t aS, uint32_t bS,
                                        int mrow, int ncol, int lane,
                                        float acc[2][4][4]) {
    const int arow = mrow + (lane & 15);
    const int asel = (lane >> 4) * 8;
    const int brow = ncol + ((lane >> 4) << 3) + (lane & 7);
    const int bsel = ((lane >> 3) & 1) * 8;
    #pragma unroll
    for (int ks = 0; ks < KSTEPS; ks++) {
        uint32_t ah[2][4], bs[2][4];
        #pragma unroll
        for (int mt = 0; mt < 2; mt++) {
            const uint32_t off = (uint32_t)(((arow + mt * 16) * STRIDE + ks * 16 + asel) * 2);
            ldsm4(ah[mt], aS + off);
        }
        #pragma unroll
        for (int j = 0; j < 2; j++) {
            const uint32_t off = (uint32_t)(((brow + j * 16) * STRIDE + ks * 16 + bsel) * 2);
            ldsm4(bs[j], bS + off);
        }
        #pragma unroll
        for (int mt = 0; mt < 2; mt++)
            #pragma unroll
            for (int nt = 0; nt < 4; nt++) {
                const int j = nt >> 1, hf = (nt & 1) * 2;
                mma_f16(acc[mt][nt], ah[mt], bs[j][hf], bs[j][hf + 1]);
            }
    }
}

// ---------------------------------------------------------------------------
// Kernel 1: P(fp16) = nf @ Wo_top, R(fp32) = nf[:N_DST] @ Wn_top  (1-pass)
// ---------------------------------------------------------------------------
#define POFF_A  0        // 128 x 136 fp16 = 34816 B
#define POFF_W  34816    // 64 x 136 fp16 = 17408 B
#define PJ_SMEM 52224
#define PJ_BLOCKS 296
#define PJ_PSPLIT 197

__global__ __launch_bounds__(256, 2)
void k_projT(const float* __restrict__ nf,
             const float* __restrict__ Wo,
             const float* __restrict__ Wn)
{
    extern __shared__ char smc[];
    const int tid = threadIdx.x, lane = tid & 31, wid = tid >> 5;
    const int mrow = (wid & 3) * 32, ncol = (wid >> 2) * 32;

    const bool isP = (blockIdx.x < PJ_PSPLIT);
    const float* W = isP ? Wo : Wn;
    const int limit = isP ? N_SRC : N_DST;
    const int ntile = (limit + 127) >> 7;
    const int t0 = isP ? blockIdx.x : (blockIdx.x - PJ_PSPLIT);
    const int ts = isP ? PJ_PSPLIT : (PJ_BLOCKS - PJ_PSPLIT);

    for (int i = tid; i < 64 * 128; i += 256) {
        const int n = i >> 7, k = i & 127;
        ((__half*)(smc + POFF_W))[n * 136 + k] = __float2half(W[k * 64 + n]);
    }
    const uint32_t aS = smem_u32(smc + POFF_A);
    const uint32_t bS = smem_u32(smc + POFF_W);

    for (int tile = t0; tile < ntile; tile += ts) {
        __syncthreads();
        const int base = tile * 128;
        // stage: 128 rows x 128 fp32 -> fp16, merged uint4 stores (2048 u4)
        #pragma unroll
        for (int t = 0; t < 8; t++) {
            const int idx = tid + 256 * t;          // 0..2047
            const int r = idx >> 4, c16 = idx & 15;
            float4 v0 = make_float4(0.f, 0.f, 0.f, 0.f), v1 = v0;
            if (base + r < limit) {
                const float4* row = (const float4*)(nf + (size_t)(base + r) * NODE_IN);
                v0 = row[c16 * 2];
                v1 = row[c16 * 2 + 1];
            }
            uint4 pk;
            pk.x = h2u(__floats2half2_rn(v0.x, v0.y));
            pk.y = h2u(__floats2half2_rn(v0.z, v0.w));
            pk.z = h2u(__floats2half2_rn(v1.x, v1.y));
            pk.w = h2u(__floats2half2_rn(v1.z, v1.w));
            *(uint4*)(smc + POFF_A + (size_t)r * 272 + c16 * 16) = pk;
        }
        __syncthreads();

        float acc[2][4][4];
        #pragma unroll
        for (int a = 0; a < 2; a++)
            #pragma unroll
            for (int b = 0; b < 4; b++)
                #pragma unroll
                for (int c = 0; c < 4; c++) acc[a][b][c] = 0.f;

        gemm_1p<8, 136>(aS, bS, mrow, ncol, lane, acc);

        #pragma unroll
        for (int mt = 0; mt < 2; mt++) {
            const int r0 = base + mrow + mt * 16 + (lane >> 2);
            #pragma unroll
            for (int nt = 0; nt < 4; nt++) {
                const int c = ncol + nt * 8 + (lane & 3) * 2;
                if (isP) {
                    if (r0 < limit)
                        *(uint32_t*)(g_P + (size_t)r0 * HID + c) =
                            h2u(__floats2half2_rn(acc[mt][nt][0], acc[mt][nt][1]));
                    if (r0 + 8 < limit)
                        *(uint32_t*)(g_P + (size_t)(r0 + 8) * HID + c) =
                            h2u(__floats2half2_rn(acc[mt][nt][2], acc[mt][nt][3]));
                } else {
                    if (r0 < limit)
                        *(float2*)(g_R + (size_t)r0 * HID + c) =
                            make_float2(acc[mt][nt][0], acc[mt][nt][1]);
                    if (r0 + 8 < limit)
                        *(float2*)(g_R + (size_t)(r0 + 8) * HID + c) =
                            make_float2(acc[mt][nt][2], acc[mt][nt][3]);
                }
            }
        }
    }
}

// ---------------------------------------------------------------------------
// Kernel 2: fused pipeline — separate e_out buffer, 3 syncs/tile,
//           GEMM3 overlaps next-tile staging
// ---------------------------------------------------------------------------
#define OFF_E    0        // 128 x 72 fp16 = 18432
#define OFF_EO   18432    // e_out buffer   = 18432
#define OFF_W1   36864
#define OFF_W2   46080
#define OFF_W3   55296
#define OFF_HN   64512    // 16 x 72 fp16 single (rows 8..15 stay zero)
#define OFF_LOG  66816    // 128 floats
#define OFF_TAU  67328
#define OFF_AMX  67360
#define OFF_V    67392
#define OFF_BE   67648
#define OFF_BO   67904
#define OFF_BN   68160
#define OFF_SRC  68416
#define OFF_C    68928
#define FS_SMEM  68944

__global__ __launch_bounds__(256, 2)
void k_fusedT(const float* __restrict__ ef,
              const int*   __restrict__ src_idx,
              const float* __restrict__ We,  const float* __restrict__ be,
              const float* __restrict__ Wa,  const float* __restrict__ ba,
              const float* __restrict__ wa,
              const float* __restrict__ Wo,  const float* __restrict__ bo,
              const float* __restrict__ Wn,  const float* __restrict__ bn,
              float* __restrict__ out)
{
    extern __shared__ char smc[];
    const int tid = threadIdx.x, lane = tid & 31, wid = tid >> 5;
    const int mrow = (wid & 3) * 32, ncol = (wid >> 2) * 32;

    float* sLog = (float*)(smc + OFF_LOG);
    float* sTau = (float*)(smc + OFF_TAU);
    float* sAmx = (float*)(smc + OFF_AMX);
    float* sV   = (float*)(smc + OFF_V);
    float* sBe  = (float*)(smc + OFF_BE);
    float* sBo  = (float*)(smc + OFF_BO);
    float* sBn  = (float*)(smc + OFF_BN);
    int*   sSrc = (int*)  (smc + OFF_SRC);

    for (int i = tid; i < 4096; i += 256) {
        const int n = i >> 6, k = i & 63;
        ((__half*)(smc + OFF_W1))[n * 72 + k] = __float2half(We[k * 64 + n]);
        ((__half*)(smc + OFF_W2))[n * 72 + k] = __float2half(Wo[(NODE_IN + k) * 64 + n]);
        ((__half*)(smc + OFF_W3))[n * 72 + k] = __float2half(Wn[(NODE_IN + k) * 64 + n]);
    }
    // zero HN pad rows 8..15 (never written again)
    for (int i = tid; i < 288; i += 256)
        ((uint32_t*)(smc + OFF_HN + 1152))[i] = 0;
    if (tid < 64) {
        sBe[tid] = be[tid]; sBo[tid] = bo[tid]; sBn[tid] = bn[tid];
        float sv = 0.f;
        #pragma unroll 8
        for (int k = 0; k < 64; k++) sv = fmaf(Wa[tid * 64 + k], wa[k], sv);
        sV[tid] = sv;
    }
    if (tid == 64) {
        float sc = 0.f;
        for (int k = 0; k < 64; k++) sc = fmaf(ba[k], wa[k], sc);
        *(float*)(smc + OFF_C) = sc;
    }
    __syncthreads();
    const float cval = *(const float*)(smc + OFF_C);

    const uint32_t eS  = smem_u32(smc + OFF_E);
    const uint32_t eoS = smem_u32(smc + OFF_EO);
    const uint32_t w1 = smem_u32(smc + OFF_W1), w2 = smem_u32(smc + OFF_W2);
    const uint32_t w3 = smem_u32(smc + OFF_W3);
    const uint32_t hnS = smem_u32(smc + OFF_HN);

    // hoist GEMM3 B fragments (loop-invariant): warp owns cols wid*8..+7
    uint32_t b3[2][4];
    {
        const int nc = wid * 8;
        #pragma unroll
        for (int g = 0; g < 2; g++) {
            const uint32_t off = (uint32_t)(((nc + (lane & 7)) * 72 + (lane >> 3) * 8 + g * 32) * 2);
            ldsm4(b3[g], w3 + off);
        }
    }

    for (int tile = blockIdx.x; tile < NTILE; tile += gridDim.x) {
        // NOTE: no guard sync — all staging targets (E, sLog, sSrc) had their
        // last readers complete before the post-epi2 sync of the previous
        // iteration; GEMM3 (prev tile) overlaps with this staging.

        // ---- stage E tile -> single fp16 (uint4 stores) + fused logits ----
        const float4* eg = (const float4*)(ef + (size_t)tile * 8192);
        #pragma unroll
        for (int t = 0; t < 4; t++) {
            const int idx = tid + 256 * t;       // 0..1023
            const int r = idx >> 3, c8 = idx & 7;
            const float4 v0 = eg[r * 16 + c8 * 2];
            const float4 v1 = eg[r * 16 + c8 * 2 + 1];
            uint4 pk;
            pk.x = h2u(__floats2half2_rn(v0.x, v0.y));
            pk.y = h2u(__floats2half2_rn(v0.z, v0.w));
            pk.z = h2u(__floats2half2_rn(v1.x, v1.y));
            pk.w = h2u(__floats2half2_rn(v1.z, v1.w));
            *(uint4*)(smc + OFF_E + (size_t)r * 144 + c8 * 16) = pk;
            const float* vv = sV + c8 * 8;
            float p = v0.x * vv[0] + v0.y * vv[1] + v0.z * vv[2] + v0.w * vv[3]
                    + v1.x * vv[4] + v1.y * vv[5] + v1.z * vv[6] + v1.w * vv[7];
            p += __shfl_xor_sync(0xffffffffu, p, 1);
            p += __shfl_xor_sync(0xffffffffu, p, 2);
            p += __shfl_xor_sync(0xffffffffu, p, 4);
            if ((tid & 7) == 0) sLog[r] = p;
        }
        if (tid < 128) sSrc[tid] = src_idx[tile * 128 + tid];
        __syncthreads();   // S1: E + logits visible

        // ---- sparsemax (8 threads of warp 0, then warp 0 joins GEMM1) ----
        if (tid < 8) {
            float z[16], amax = -3.4e38f;
            #pragma unroll
            for (int d = 0; d < 16; d++) {
                float raw = sLog[tid * 16 + d] + cval;
                raw = (raw > 0.f) ? raw : 0.01f * raw;
                sLog[tid * 16 + d] = raw;
                z[d] = raw; amax = fmaxf(amax, z[d]);
            }
            #pragma unroll
            for (int d = 0; d < 16; d++) z[d] -= amax;
            #pragma unroll
            for (int kk2 = 2; kk2 <= 16; kk2 <<= 1)
                #pragma unroll
                for (int j = kk2 >> 1; j > 0; j >>= 1)
                    #pragma unroll
                    for (int i = 0; i < 16; i++) {
                        const int l = i ^ j;
                        if (l > i) {
                            const bool up = ((i & kk2) == 0);
                            const float a0 = z[i], b0 = z[l];
                            if (up ? (a0 > b0) : (a0 < b0)) { z[i] = b0; z[l] = a0; }
                        }
                    }
            float cs = 0.f, cssel = 0.f, kk = 1.f;
            #pragma unroll
            for (int j = 1; j <= 16; j++) {
                const float zz = z[16 - j];
                cs += zz;
                if (1.f + (float)j * zz > cs) { kk = (float)j; cssel = cs; }
            }
            sTau[tid] = (cssel - 1.f) / kk;
            sAmx[tid] = amax;
        }

        float acc[2][4][4];

        // ---- GEMM1: e_out_pre = E @ We^T ----
        #pragma unroll
        for (int a = 0; a < 2; a++)
            #pragma unroll
            for (int b = 0; b < 4; b++)
                #pragma unroll
                for (int c = 0; c < 4; c++) acc[a][b][c] = 0.f;
        gemm_1p<4, 72>(eS, w1, mrow, ncol, lane, acc);

        // ---- epilogue1: relu(+be) -> separate e_out buffer ----
        #pragma unroll
        for (int mt = 0; mt < 2; mt++) {
            const int r0 = mrow + mt * 16 + (lane >> 2);
            #pragma unroll
            for (int nt = 0; nt < 4; nt++) {
                const int c = ncol + nt * 8 + (lane & 3) * 2;
                const float x0 = fmaxf(acc[mt][nt][0] + sBe[c],     0.f);
                const float x1 = fmaxf(acc[mt][nt][1] + sBe[c + 1], 0.f);
                const float x2 = fmaxf(acc[mt][nt][2] + sBe[c],     0.f);
                const float x3 = fmaxf(acc[mt][nt][3] + sBe[c + 1], 0.f);
                *(uint32_t*)(smc + OFF_EO + (size_t)(r0 * 72 + c) * 2) =
                    h2u(__floats2half2_rn(x0, x1));
                *(uint32_t*)(smc + OFF_EO + (size_t)((r0 + 8) * 72 + c) * 2) =
                    h2u(__floats2half2_rn(x2, x3));
            }
        }
        __syncthreads();   // S2: e_out visible (tau also done: warp0 pre-GEMM1)

        // ---- GEMM2: m_pre = e_out @ Wo_bot^T ----
        #pragma unroll
        for (int a = 0; a < 2; a++)
            #pragma unroll
            for (int b = 0; b < 4; b++)
                #pragma unroll
                for (int c = 0; c < 4; c++) acc[a][b][c] = 0.f;
        gemm_1p<4, 72>(eoS, w2, mrow, ncol, lane, acc);

        // ---- epilogue2: m = relu(m_pre + P[src] + bo); alpha-weighted sum ----
        #pragma unroll
        for (int mt = 0; mt < 2; mt++) {
            const int ln = (mrow >> 4) + mt;
            const int r0 = mrow + mt * 16 + (lane >> 2);
            const int r1 = r0 + 8;
            const int s0 = sSrc[r0], s1 = sSrc[r1];
            const float at = sAmx[ln] + sTau[ln];
            const float al0 = fmaxf(sLog[r0] - at, 0.f);
            const float al1 = fmaxf(sLog[r1] - at, 0.f);
            #pragma unroll
            for (int nt = 0; nt < 4; nt++) {
                const int c = ncol + nt * 8 + (lane & 3) * 2;
                const uint32_t pv0 = *(const uint32_t*)(g_P + (size_t)s0 * HID + c);
                const uint32_t pv1 = *(const uint32_t*)(g_P + (size_t)s1 * HID + c);
                const float2 p0 = __half22float2(*(const __half2*)&pv0);
                const float2 p1 = __half22float2(*(const __half2*)&pv1);
                const float m00 = fmaxf(acc[mt][nt][0] + p0.x + sBo[c],     0.f);
                const float m01 = fmaxf(acc[mt][nt][1] + p0.y + sBo[c + 1], 0.f);
                const float m10 = fmaxf(acc[mt][nt][2] + p1.x + sBo[c],     0.f);
                const float m11 = fmaxf(acc[mt][nt][3] + p1.y + sBo[c + 1], 0.f);
                float sx = m00 * al0 + m10 * al1;
                float sy = m01 * al0 + m11 * al1;
                sx += __shfl_xor_sync(0xffffffffu, sx, 4);
                sy += __shfl_xor_sync(0xffffffffu, sy, 4);
                sx += __shfl_xor_sync(0xffffffffu, sx, 8);
                sy += __shfl_xor_sync(0xffffffffu, sy, 8);
                sx += __shfl_xor_sync(0xffffffffu, sx, 16);
                sy += __shfl_xor_sync(0xffffffffu, sy, 16);
                if (lane < 4)
                    *(uint32_t*)(smc + OFF_HN + (size_t)(ln * 72 + c) * 2) =
                        h2u(__floats2half2_rn(sx, sy));
            }
        }
        __syncthreads();   // S3: HN visible

        // ---- GEMM3 (MMA, M=16 padded, 1-pass): out = relu(R + HN@Wn^T + bn) ----
        {
            float acc3[4] = {0.f, 0.f, 0.f, 0.f};
            #pragma unroll
            for (int ks = 0; ks < 4; ks++) {
                uint32_t a3[4];
                const uint32_t aoff = (uint32_t)(((lane & 15) * 72 + ks * 16 + (lane >> 4) * 8) * 2);
                ldsm4(a3, hnS + aoff);
                const int g = ks >> 1, pr = (ks & 1) * 2;
                mma_f16(acc3, a3, b3[g][pr], b3[g][pr + 1]);
            }
            const int node = tile * 8 + (lane >> 2);
            const int col = wid * 8 + (lane & 3) * 2;
            const float2 r2 = *(const float2*)(g_R + (size_t)node * HID + col);
            const float o0 = acc3[0] + r2.x + sBn[col];
            const float o1 = acc3[1] + r2.y + sBn[col + 1];
            *(float2*)(out + (size_t)node * HID + col) =
                make_float2(fmaxf(o0, 0.f), fmaxf(o1, 0.f));
        }
        // no sync: next staging does not touch HN; S3 already separates
        // this tile's HN writes from GEMM3 reads, and next-tile epi2 HN
        // writes are fenced behind next S1+S2.
    }
}

// ---------------------------------------------------------------------------
extern "C" void kernel_launch(void* const* d_in, const int* in_sizes, int n_in,
                              void* d_out, int out_size)
{
    const float* nf = (const float*)d_in[0];
    const float* ef = (const float*)d_in[1];
    const int*   si = (const int*)  d_in[2];
    const float* We = (const float*)d_in[3];
    const float* be = (const float*)d_in[4];
    const float* Wa = (const float*)d_in[5];
    const float* ba = (const float*)d_in[6];
    const float* wa = (const float*)d_in[7];
    const float* Wo = (const float*)d_in[8];
    const float* bo = (const float*)d_in[9];
    const float* Wn = (const float*)d_in[10];
    const float* bn = (const float*)d_in[11];
    float* out = (float*)d_out;

    cudaFuncSetAttribute(k_projT,  cudaFuncAttributeMaxDynamicSharedMemorySize, PJ_SMEM);
    cudaFuncSetAttribute(k_fusedT, cudaFuncAttributeMaxDynamicSharedMemorySize, FS_SMEM);

    k_projT<<<PJ_BLOCKS, 256, PJ_SMEM>>>(nf, Wo, Wn);
    k_fusedT<<<296, 256, FS_SMEM>>>(ef, si, We, be, Wa, ba, wa, Wo, bo, Wn, bn, out);
}